// round 1
// baseline (speedup 1.0000x reference)
#include <cuda_runtime.h>
#include <cuda_bf16.h>
#include <math.h>

#define NN 4096
#define NW 128          // NN/32 mask words per row
#define H 4
#define F1 128          // head dim layer 1
#define F2 32           // head dim layer 2
#define IN_F 512
#define HID1 64
#define OUT_F 16
#define LRELU 0.2f
#define BN_EPS 1e-5f

// ---------------- scratch (static device allocations are allowed) ----------------
__device__ float    g_h1[NN * 512];     // x @ W1         [N, H*F1]
__device__ float    g_x1[NN * 512];     // gat1 out       [N, H*F1]
__device__ float    g_x2[NN * HID1];    // lin1+bn+elu    [N, 64]
__device__ float    g_h2[NN * 128];     // x2 @ W2        [N, H*F2]
__device__ float    g_x3[NN * 128];     // gat2 out       [N, H*F2]
__device__ float    g_z4[NN * OUT_F];   // lin2 preact    [N, 16]
__device__ float    g_es1[H * NN], g_ed1[H * NN];
__device__ float    g_es2[H * NN], g_ed2[H * NN];
__device__ unsigned g_mask[NN * NW];    // adjacency bitmask
__device__ float    g_mean[64], g_rstd[64];

// ---------------- adjacency -> bitmask ----------------
__global__ void k_pack_mask(const int* __restrict__ adj) {
    int gw   = (blockIdx.x * blockDim.x + threadIdx.x) >> 5;   // global warp id = word id
    int lane = threadIdx.x & 31;
    int i  = gw >> 7;        // row
    int wj = gw & 127;       // word within row
    int v = adj[i * NN + wj * 32 + lane];
    unsigned m = __ballot_sync(0xffffffffu, v > 0);
    if (lane == 0) g_mask[gw] = m;
}

// ---------------- generic tiled fp32 GEMM (+ optional bias) ----------------
// C[M,Nn] = A[M,K] @ B[K,Nn] (+ bias). All dims divisible by tile params.
template <int BM, int BN, int BK, int TM, int TN>
__global__ void k_gemm_bias(const float* __restrict__ A, const float* __restrict__ B,
                            const float* __restrict__ bias, float* __restrict__ C,
                            int M, int Nn, int K) {
    constexpr int THREADS = (BM / TM) * (BN / TN);
    __shared__ float As[BM][BK + 1];
    __shared__ float Bs[BK][BN + 1];
    int tid = threadIdx.x;
    int rm = tid / (BN / TN);
    int rn = tid % (BN / TN);
    int m0 = blockIdx.y * BM, n0 = blockIdx.x * BN;
    float acc[TM][TN];
#pragma unroll
    for (int m = 0; m < TM; m++)
#pragma unroll
        for (int n = 0; n < TN; n++) acc[m][n] = 0.f;

    for (int k0 = 0; k0 < K; k0 += BK) {
        for (int idx = tid; idx < BM * BK; idx += THREADS) {
            int r = idx / BK, c = idx % BK;
            As[r][c] = A[(size_t)(m0 + r) * K + k0 + c];
        }
        for (int idx = tid; idx < BK * BN; idx += THREADS) {
            int r = idx / BN, c = idx % BN;
            Bs[r][c] = B[(size_t)(k0 + r) * Nn + n0 + c];
        }
        __syncthreads();
#pragma unroll
        for (int kk = 0; kk < BK; kk++) {
            float a[TM], b[TN];
#pragma unroll
            for (int m = 0; m < TM; m++) a[m] = As[rm * TM + m][kk];
#pragma unroll
            for (int n = 0; n < TN; n++) b[n] = Bs[kk][rn * TN + n];
#pragma unroll
            for (int m = 0; m < TM; m++)
#pragma unroll
                for (int n = 0; n < TN; n++) acc[m][n] = fmaf(a[m], b[n], acc[m][n]);
        }
        __syncthreads();
    }
#pragma unroll
    for (int m = 0; m < TM; m++) {
        int row = m0 + rm * TM + m;
#pragma unroll
        for (int n = 0; n < TN; n++) {
            int col = n0 + rn * TN + n;
            float v = acc[m][n];
            if (bias) v += bias[col];
            C[(size_t)row * Nn + col] = v;
        }
    }
}

// ---------------- per-node attention scores: es/ed = h . a ----------------
template <int F>
__global__ void k_attn_scores(const float* __restrict__ hfeat,
                              const float* __restrict__ a_src,
                              const float* __restrict__ a_dst,
                              float* __restrict__ es, float* __restrict__ ed) {
    int n = blockIdx.x * (blockDim.x >> 5) + (threadIdx.x >> 5);
    int lane = threadIdx.x & 31;
    if (n >= NN) return;
    const float* row = hfeat + (size_t)n * (H * F);
#pragma unroll
    for (int h = 0; h < H; h++) {
        float ss = 0.f, sd = 0.f;
        for (int k = lane; k < F; k += 32) {
            float v = row[h * F + k];
            ss = fmaf(v, a_src[h * F + k], ss);
            sd = fmaf(v, a_dst[h * F + k], sd);
        }
#pragma unroll
        for (int o = 16; o; o >>= 1) {
            ss += __shfl_xor_sync(0xffffffffu, ss, o);
            sd += __shfl_xor_sync(0xffffffffu, sd, o);
        }
        if (lane == 0) { es[h * NN + n] = ss; ed[h * NN + n] = sd; }
    }
}

// ---------------- GAT layer 1 aggregation (F=128 per head) ----------------
// grid: (NN/32, H), 256 threads. Out tile: 32 rows x 128 cols (one head).
__global__ void k_gat1(const float* __restrict__ hfeat,
                       const float* __restrict__ es, const float* __restrict__ ed,
                       float* __restrict__ out) {
    __shared__ float hs[32][128];
    __shared__ float ws[32][33];
    __shared__ float eds[32];
    __shared__ float esr[32];
    __shared__ unsigned mrow[32];
    int t = threadIdx.x;
    int head = blockIdx.y;
    int i0 = blockIdx.x * 32;
    int il = t & 31;
    int fg = t >> 5;
    int f0 = fg * 16;
    if (t < 32) esr[t] = es[head * NN + i0 + t];

    float acc[16];
#pragma unroll
    for (int k = 0; k < 16; k++) acc[k] = 0.f;
    float denom = 0.f;

    for (int jc = 0; jc < NN / 32; jc++) {
        __syncthreads();
#pragma unroll
        for (int q = 0; q < 4; q++) {
            int v = t + q * 256;
            int j = v >> 5, f4 = v & 31;
            float4 hv = *(const float4*)&hfeat[(size_t)(jc * 32 + j) * 512 + head * 128 + f4 * 4];
            *(float4*)&hs[j][f4 * 4] = hv;
        }
        if (t < 32) {
            eds[t]  = ed[head * NN + jc * 32 + t];
            mrow[t] = g_mask[(size_t)(i0 + t) * NW + jc];
        }
        __syncthreads();
#pragma unroll
        for (int q = 0; q < 4; q++) {
            int v = t + q * 256;
            int i = v >> 5, j = v & 31;
            float e = esr[i] + eds[j];
            e = e > 0.f ? e : LRELU * e;
            ws[i][j] = ((mrow[i] >> j) & 1u) ? __expf(e) : 0.f;
        }
        __syncthreads();
#pragma unroll 4
        for (int j = 0; j < 32; j++) {
            float w = ws[il][j];
            denom += w;
            const float4* hp = (const float4*)&hs[j][f0];
            float4 a0 = hp[0], a1 = hp[1], a2 = hp[2], a3 = hp[3];
            acc[0]  = fmaf(w, a0.x, acc[0]);  acc[1]  = fmaf(w, a0.y, acc[1]);
            acc[2]  = fmaf(w, a0.z, acc[2]);  acc[3]  = fmaf(w, a0.w, acc[3]);
            acc[4]  = fmaf(w, a1.x, acc[4]);  acc[5]  = fmaf(w, a1.y, acc[5]);
            acc[6]  = fmaf(w, a1.z, acc[6]);  acc[7]  = fmaf(w, a1.w, acc[7]);
            acc[8]  = fmaf(w, a2.x, acc[8]);  acc[9]  = fmaf(w, a2.y, acc[9]);
            acc[10] = fmaf(w, a2.z, acc[10]); acc[11] = fmaf(w, a2.w, acc[11]);
            acc[12] = fmaf(w, a3.x, acc[12]); acc[13] = fmaf(w, a3.y, acc[13]);
            acc[14] = fmaf(w, a3.z, acc[14]); acc[15] = fmaf(w, a3.w, acc[15]);
        }
    }
    float inv = 1.f / denom;
    float* op = &out[(size_t)(i0 + il) * 512 + head * 128 + f0];
#pragma unroll
    for (int q = 0; q < 4; q++) {
        float4 v;
        v.x = acc[q * 4 + 0] * inv; v.y = acc[q * 4 + 1] * inv;
        v.z = acc[q * 4 + 2] * inv; v.w = acc[q * 4 + 3] * inv;
        *(float4*)&op[q * 4] = v;
    }
}

// ---------------- GAT layer 2 aggregation (F=32 per head) ----------------
// grid: (NN/32, H), 256 threads. Out tile: 32 rows x 32 cols (one head).
__global__ void k_gat2(const float* __restrict__ hfeat,
                       const float* __restrict__ es, const float* __restrict__ ed,
                       float* __restrict__ out) {
    __shared__ float hs[32][36];   // stride 36 keeps float4 alignment
    __shared__ float ws[32][33];
    __shared__ float eds[32];
    __shared__ float esr[32];
    __shared__ unsigned mrow[32];
    int t = threadIdx.x;
    int head = blockIdx.y;
    int i0 = blockIdx.x * 32;
    int il = t & 31;
    int fg = t >> 5;      // 0..7
    int f0 = fg * 4;
    if (t < 32) esr[t] = es[head * NN + i0 + t];

    float acc[4] = {0.f, 0.f, 0.f, 0.f};
    float denom = 0.f;

    for (int jc = 0; jc < NN / 32; jc++) {
        __syncthreads();
        {
            int v = t;                    // 1024 elems / 256 threads = 4, do with stride
            #pragma unroll
            for (int q = 0; q < 4; q++) {
                int u = v + q * 256;
                int j = u >> 5, f = u & 31;
                hs[j][f] = hfeat[(size_t)(jc * 32 + j) * 128 + head * 32 + f];
            }
        }
        if (t < 32) {
            eds[t]  = ed[head * NN + jc * 32 + t];
            mrow[t] = g_mask[(size_t)(i0 + t) * NW + jc];
        }
        __syncthreads();
#pragma unroll
        for (int q = 0; q < 4; q++) {
            int v = t + q * 256;
            int i = v >> 5, j = v & 31;
            float e = esr[i] + eds[j];
            e = e > 0.f ? e : LRELU * e;
            ws[i][j] = ((mrow[i] >> j) & 1u) ? __expf(e) : 0.f;
        }
        __syncthreads();
#pragma unroll 4
        for (int j = 0; j < 32; j++) {
            float w = ws[il][j];
            denom += w;
            float4 hv = *(const float4*)&hs[j][f0];
            acc[0] = fmaf(w, hv.x, acc[0]);
            acc[1] = fmaf(w, hv.y, acc[1]);
            acc[2] = fmaf(w, hv.z, acc[2]);
            acc[3] = fmaf(w, hv.w, acc[3]);
        }
    }
    float inv = 1.f / denom;
    float4 v;
    v.x = acc[0] * inv; v.y = acc[1] * inv; v.z = acc[2] * inv; v.w = acc[3] * inv;
    *(float4*)&out[(size_t)(i0 + il) * 128 + head * 32 + f0] = v;
}

// ---------------- batchnorm statistics (per column) ----------------
__global__ void k_bn_stats(const float* __restrict__ z, int C,
                           float* __restrict__ mean, float* __restrict__ rstd) {
    int c = blockIdx.x;
    double ds = 0.0, ds2 = 0.0;
    for (int r = threadIdx.x; r < NN; r += blockDim.x) {
        float v = z[(size_t)r * C + c];
        ds += v; ds2 += (double)v * v;
    }
    __shared__ double sh[256], sh2[256];
    sh[threadIdx.x] = ds; sh2[threadIdx.x] = ds2;
    __syncthreads();
    for (int o = 128; o; o >>= 1) {
        if (threadIdx.x < o) { sh[threadIdx.x] += sh[threadIdx.x + o]; sh2[threadIdx.x] += sh2[threadIdx.x + o]; }
        __syncthreads();
    }
    if (threadIdx.x == 0) {
        double mu = sh[0] / NN;
        double var = sh2[0] / NN - mu * mu;
        mean[c] = (float)mu;
        rstd[c] = rsqrtf((float)var + BN_EPS);
    }
}

// ---------------- BN apply + ELU ----------------
__global__ void k_bn_elu(const float* __restrict__ z, const float* __restrict__ mean,
                         const float* __restrict__ rstd, const float* __restrict__ gamma,
                         const float* __restrict__ beta, float* __restrict__ out, int C) {
    int idx = blockIdx.x * blockDim.x + threadIdx.x;
    int c = idx % C;
    float v = (z[idx] - mean[c]) * rstd[c] * gamma[c] + beta[c];
    out[idx] = v > 0.f ? v : (expf(v) - 1.f);
}

// ---------------- launch ----------------
extern "C" void kernel_launch(void* const* d_in, const int* in_sizes, int n_in,
                              void* d_out, int out_size) {
    const float* x   = (const float*)d_in[0];
    const int*   adj = (const int*)d_in[1];
    const float* W1  = (const float*)d_in[2];
    const float* a1s = (const float*)d_in[3];
    const float* a1d = (const float*)d_in[4];
    const float* lw1 = (const float*)d_in[5];
    const float* lb1 = (const float*)d_in[6];
    const float* g1  = (const float*)d_in[7];
    const float* be1 = (const float*)d_in[8];
    const float* W2  = (const float*)d_in[9];
    const float* a2s = (const float*)d_in[10];
    const float* a2d = (const float*)d_in[11];
    const float* lw2 = (const float*)d_in[12];
    const float* lb2 = (const float*)d_in[13];
    const float* g2  = (const float*)d_in[14];
    const float* be2 = (const float*)d_in[15];
    float* out = (float*)d_out;

    float *h1, *x1, *x2, *h2, *x3, *z4, *es1, *ed1, *es2, *ed2, *mean, *rstd;
    cudaGetSymbolAddress((void**)&h1, g_h1);
    cudaGetSymbolAddress((void**)&x1, g_x1);
    cudaGetSymbolAddress((void**)&x2, g_x2);
    cudaGetSymbolAddress((void**)&h2, g_h2);
    cudaGetSymbolAddress((void**)&x3, g_x3);
    cudaGetSymbolAddress((void**)&z4, g_z4);
    cudaGetSymbolAddress((void**)&es1, g_es1);
    cudaGetSymbolAddress((void**)&ed1, g_ed1);
    cudaGetSymbolAddress((void**)&es2, g_es2);
    cudaGetSymbolAddress((void**)&ed2, g_ed2);
    cudaGetSymbolAddress((void**)&mean, g_mean);
    cudaGetSymbolAddress((void**)&rstd, g_rstd);

    // 1) adjacency -> bitmask
    k_pack_mask<<<(NN * NN) / 256, 256>>>(adj);

    // 2) h1 = x @ W1   [4096,512]x[512,512]
    k_gemm_bias<128, 64, 16, 8, 4><<<dim3(512 / 64, NN / 128), 256>>>(x, W1, nullptr, h1, NN, 512, 512);

    // 3) attention scores layer 1
    k_attn_scores<F1><<<NN / 8, 256>>>(h1, a1s, a1d, es1, ed1);

    // 4) GAT1 aggregation -> x1
    k_gat1<<<dim3(NN / 32, H), 256>>>(h1, es1, ed1, x1);

    // 5) z2 = x1 @ lw1 + lb1   [4096,512]x[512,64]
    k_gemm_bias<128, 64, 16, 8, 4><<<dim3(1, NN / 128), 256>>>(x1, lw1, lb1, x2, NN, HID1, 512);

    // 6-7) BN + ELU (in place on x2)
    k_bn_stats<<<HID1, 256>>>(x2, HID1, mean, rstd);
    k_bn_elu<<<(NN * HID1) / 256, 256>>>(x2, mean, rstd, g1, be1, x2, HID1);

    // 8) h2 = x2 @ W2   [4096,64]x[64,128]
    k_gemm_bias<128, 64, 16, 8, 4><<<dim3(2, NN / 128), 256>>>(x2, W2, nullptr, h2, NN, 128, 64);

    // 9) attention scores layer 2
    k_attn_scores<F2><<<NN / 8, 256>>>(h2, a2s, a2d, es2, ed2);

    // 10) GAT2 aggregation -> x3
    k_gat2<<<dim3(NN / 32, H), 256>>>(h2, es2, ed2, x3);

    // 11) z4 = x3 @ lw2 + lb2  [4096,128]x[128,16]
    k_gemm_bias<128, 16, 16, 8, 4><<<dim3(1, NN / 128), 64>>>(x3, lw2, lb2, z4, NN, OUT_F, 128);

    // 12-13) BN + ELU -> output
    k_bn_stats<<<OUT_F, 256>>>(z4, OUT_F, mean, rstd);
    k_bn_elu<<<(NN * OUT_F) / 256, 256>>>(z4, mean, rstd, g2, be2, out, OUT_F);
}

// round 2
// speedup vs baseline: 1.2174x; 1.2174x over previous
#include <cuda_runtime.h>
#include <cuda_bf16.h>
#include <math.h>

#define NN 4096
#define NW 128          // NN/32 mask words per row
#define H 4
#define F1 128
#define F2 32
#define IN_F 512
#define HID1 64
#define OUT_F 16
#define LRELU 0.2f
#define BN_EPS 1e-5f

// ---------------- scratch ----------------
__device__ float    g_h1[NN * 512];
__device__ float    g_x1[NN * 512];
__device__ float    g_x2[NN * HID1];
__device__ float    g_h2[NN * 128];
__device__ float    g_x3[NN * 128];
__device__ float    g_z4[NN * OUT_F];
// score arrays: [0]=es,[1]=exp(es),[2]=exp(.2es),[3]=ed,[4]=exp(ed),[5]=exp(.2ed), each H*NN
__device__ float    g_sc1[6 * H * NN];
__device__ float    g_sc2[6 * H * NN];
__device__ unsigned g_mask[NN * NW];
__device__ float    g_mean[64], g_rstd[64];

// ---------------- adjacency -> bitmask ----------------
__global__ void k_pack_mask(const int* __restrict__ adj) {
    int gw   = (blockIdx.x * blockDim.x + threadIdx.x) >> 5;
    int lane = threadIdx.x & 31;
    int i  = gw >> 7;
    int wj = gw & 127;
    int v = adj[i * NN + wj * 32 + lane];
    unsigned m = __ballot_sync(0xffffffffu, v > 0);
    if (lane == 0) g_mask[gw] = m;
}

// ---------------- generic tiled fp32 GEMM (+ optional bias) ----------------
template <int BM, int BN, int BK, int TM, int TN>
__global__ void k_gemm_bias(const float* __restrict__ A, const float* __restrict__ B,
                            const float* __restrict__ bias, float* __restrict__ C,
                            int M, int Nn, int K) {
    constexpr int THREADS = (BM / TM) * (BN / TN);
    __shared__ float As[BM][BK + 1];
    __shared__ float Bs[BK][BN + 1];
    int tid = threadIdx.x;
    int rm = tid / (BN / TN);
    int rn = tid % (BN / TN);
    int m0 = blockIdx.y * BM, n0 = blockIdx.x * BN;
    float acc[TM][TN];
#pragma unroll
    for (int m = 0; m < TM; m++)
#pragma unroll
        for (int n = 0; n < TN; n++) acc[m][n] = 0.f;

    for (int k0 = 0; k0 < K; k0 += BK) {
        for (int idx = tid; idx < BM * BK; idx += THREADS) {
            int r = idx / BK, c = idx % BK;
            As[r][c] = A[(size_t)(m0 + r) * K + k0 + c];
        }
        for (int idx = tid; idx < BK * BN; idx += THREADS) {
            int r = idx / BN, c = idx % BN;
            Bs[r][c] = B[(size_t)(k0 + r) * Nn + n0 + c];
        }
        __syncthreads();
#pragma unroll
        for (int kk = 0; kk < BK; kk++) {
            float a[TM], b[TN];
#pragma unroll
            for (int m = 0; m < TM; m++) a[m] = As[rm * TM + m][kk];
#pragma unroll
            for (int n = 0; n < TN; n++) b[n] = Bs[kk][rn * TN + n];
#pragma unroll
            for (int m = 0; m < TM; m++)
#pragma unroll
                for (int n = 0; n < TN; n++) acc[m][n] = fmaf(a[m], b[n], acc[m][n]);
        }
        __syncthreads();
    }
#pragma unroll
    for (int m = 0; m < TM; m++) {
        int row = m0 + rm * TM + m;
#pragma unroll
        for (int n = 0; n < TN; n++) {
            int col = n0 + rn * TN + n;
            float v = acc[m][n];
            if (bias) v += bias[col];
            C[(size_t)row * Nn + col] = v;
        }
    }
}

// ---------------- per-node scores + precomputed exps ----------------
template <int F>
__global__ void k_attn_scores(const float* __restrict__ hfeat,
                              const float* __restrict__ a_src,
                              const float* __restrict__ a_dst,
                              float* __restrict__ sc) {
    int n = blockIdx.x * (blockDim.x >> 5) + (threadIdx.x >> 5);
    int lane = threadIdx.x & 31;
    if (n >= NN) return;
    const float* row = hfeat + (size_t)n * (H * F);
#pragma unroll
    for (int h = 0; h < H; h++) {
        float ss = 0.f, sd = 0.f;
        for (int k = lane; k < F; k += 32) {
            float v = row[h * F + k];
            ss = fmaf(v, a_src[h * F + k], ss);
            sd = fmaf(v, a_dst[h * F + k], sd);
        }
#pragma unroll
        for (int o = 16; o; o >>= 1) {
            ss += __shfl_xor_sync(0xffffffffu, ss, o);
            sd += __shfl_xor_sync(0xffffffffu, sd, o);
        }
        if (lane == 0) {
            int idx = h * NN + n;
            sc[0 * H * NN + idx] = ss;
            sc[1 * H * NN + idx] = expf(ss);
            sc[2 * H * NN + idx] = expf(LRELU * ss);
            sc[3 * H * NN + idx] = sd;
            sc[4 * H * NN + idx] = expf(sd);
            sc[5 * H * NN + idx] = expf(LRELU * sd);
        }
    }
}

// ---------------- GAT layer 1 aggregation (F=128), 64x128 tile ----------------
__global__ __launch_bounds__(256, 2) void k_gat1(const float* __restrict__ hfeat,
                                                 const float* __restrict__ sc,
                                                 float* __restrict__ out) {
    __shared__ float hs[32][132];
    __shared__ float ws[64][36];
    __shared__ float edr[32], Edv[32], ed2[32];
    __shared__ unsigned mw[64];
    __shared__ float dpart[4][64];
    __shared__ float dinv[64];

    int t = threadIdx.x;
    int head = blockIdx.y;
    int i0 = blockIdx.x * 64;
    int rm = t >> 5;        // 0..7 -> rows rm*8..+7
    int rn = t & 31;        // cols rn*4..+3
    int wi = t & 63;        // w-gen row
    int wj0 = (t >> 6) * 8; // w-gen j start

    float es_i = sc[0 * H * NN + head * NN + i0 + wi];
    float E_i  = sc[1 * H * NN + head * NN + i0 + wi];
    float e_i  = sc[2 * H * NN + head * NN + i0 + wi];
    float dsum = 0.f;
    float acc[8][4];
#pragma unroll
    for (int m = 0; m < 8; m++)
#pragma unroll
        for (int n = 0; n < 4; n++) acc[m][n] = 0.f;

    for (int jc = 0; jc < NN / 32; jc++) {
        __syncthreads();
#pragma unroll
        for (int q = 0; q < 4; q++) {
            int idx = t + q * 256;
            int j = idx >> 5, f4 = idx & 31;
            *(float4*)&hs[j][f4 * 4] =
                *(const float4*)&hfeat[(size_t)(jc * 32 + j) * 512 + head * 128 + f4 * 4];
        }
        if (t < 32) {
            edr[t] = sc[3 * H * NN + head * NN + jc * 32 + t];
            Edv[t] = sc[4 * H * NN + head * NN + jc * 32 + t];
            ed2[t] = sc[5 * H * NN + head * NN + jc * 32 + t];
        } else if (t < 96) {
            mw[t - 32] = g_mask[(size_t)(i0 + t - 32) * NW + jc];
        }
        __syncthreads();
        unsigned m = mw[wi];
#pragma unroll
        for (int q = 0; q < 8; q++) {
            int j = wj0 + q;
            float s = es_i + edr[j];
            float w = (s > 0.f) ? E_i * Edv[j] : e_i * ed2[j];
            w = ((m >> j) & 1u) ? w : 0.f;
            ws[wi][j] = w;
            dsum += w;
        }
        __syncthreads();
#pragma unroll 2
        for (int j4 = 0; j4 < 32; j4 += 4) {
            float4 hv0 = *(float4*)&hs[j4 + 0][rn * 4];
            float4 hv1 = *(float4*)&hs[j4 + 1][rn * 4];
            float4 hv2 = *(float4*)&hs[j4 + 2][rn * 4];
            float4 hv3 = *(float4*)&hs[j4 + 3][rn * 4];
#pragma unroll
            for (int m8 = 0; m8 < 8; m8++) {
                float4 w4 = *(float4*)&ws[rm * 8 + m8][j4];
                acc[m8][0] = fmaf(w4.x, hv0.x, acc[m8][0]);
                acc[m8][1] = fmaf(w4.x, hv0.y, acc[m8][1]);
                acc[m8][2] = fmaf(w4.x, hv0.z, acc[m8][2]);
                acc[m8][3] = fmaf(w4.x, hv0.w, acc[m8][3]);
                acc[m8][0] = fmaf(w4.y, hv1.x, acc[m8][0]);
                acc[m8][1] = fmaf(w4.y, hv1.y, acc[m8][1]);
                acc[m8][2] = fmaf(w4.y, hv1.z, acc[m8][2]);
                acc[m8][3] = fmaf(w4.y, hv1.w, acc[m8][3]);
                acc[m8][0] = fmaf(w4.z, hv2.x, acc[m8][0]);
                acc[m8][1] = fmaf(w4.z, hv2.y, acc[m8][1]);
                acc[m8][2] = fmaf(w4.z, hv2.z, acc[m8][2]);
                acc[m8][3] = fmaf(w4.z, hv2.w, acc[m8][3]);
                acc[m8][0] = fmaf(w4.w, hv3.x, acc[m8][0]);
                acc[m8][1] = fmaf(w4.w, hv3.y, acc[m8][1]);
                acc[m8][2] = fmaf(w4.w, hv3.z, acc[m8][2]);
                acc[m8][3] = fmaf(w4.w, hv3.w, acc[m8][3]);
            }
        }
    }
    dpart[t >> 6][wi] = dsum;
    __syncthreads();
    if (t < 64) {
        float d = dpart[0][t] + dpart[1][t] + dpart[2][t] + dpart[3][t];
        dinv[t] = 1.f / d;
    }
    __syncthreads();
#pragma unroll
    for (int m8 = 0; m8 < 8; m8++) {
        int row = rm * 8 + m8;
        float inv = dinv[row];
        float4 v;
        v.x = acc[m8][0] * inv; v.y = acc[m8][1] * inv;
        v.z = acc[m8][2] * inv; v.w = acc[m8][3] * inv;
        *(float4*)&out[(size_t)(i0 + row) * 512 + head * 128 + rn * 4] = v;
    }
}

// ---------------- GAT layer 2 aggregation (F=32), 128x32 tile ----------------
__global__ __launch_bounds__(256, 2) void k_gat2(const float* __restrict__ hfeat,
                                                 const float* __restrict__ sc,
                                                 float* __restrict__ out) {
    __shared__ float hs[32][36];
    __shared__ float ws[128][36];
    __shared__ float edr[32], Edv[32], ed2[32];
    __shared__ unsigned mw[128];
    __shared__ float dpart[2][128];
    __shared__ float dinv[128];

    int t = threadIdx.x;
    int head = blockIdx.y;
    int i0 = blockIdx.x * 128;
    int rm = t >> 4;          // 0..15 -> rows rm*8..+7
    int rn = t & 15;          // cols rn*2..+1
    int wi = t & 127;         // w-gen row
    int wj0 = (t >> 7) * 16;  // w-gen j start (0 or 16)

    float es_i = sc[0 * H * NN + head * NN + i0 + wi];
    float E_i  = sc[1 * H * NN + head * NN + i0 + wi];
    float e_i  = sc[2 * H * NN + head * NN + i0 + wi];
    float dsum = 0.f;
    float acc[8][2];
#pragma unroll
    for (int m = 0; m < 8; m++) { acc[m][0] = 0.f; acc[m][1] = 0.f; }

    for (int jc = 0; jc < NN / 32; jc++) {
        __syncthreads();
        {
            int j = t >> 3, f4 = t & 7;
            *(float4*)&hs[j][f4 * 4] =
                *(const float4*)&hfeat[(size_t)(jc * 32 + j) * 128 + head * 32 + f4 * 4];
        }
        if (t < 32) {
            edr[t] = sc[3 * H * NN + head * NN + jc * 32 + t];
            Edv[t] = sc[4 * H * NN + head * NN + jc * 32 + t];
            ed2[t] = sc[5 * H * NN + head * NN + jc * 32 + t];
        }
        if (t >= 128) {
            mw[t - 128] = g_mask[(size_t)(i0 + t - 128) * NW + jc];
        }
        __syncthreads();
        unsigned m = mw[wi];
#pragma unroll
        for (int q = 0; q < 16; q++) {
            int j = wj0 + q;
            float s = es_i + edr[j];
            float w = (s > 0.f) ? E_i * Edv[j] : e_i * ed2[j];
            w = ((m >> j) & 1u) ? w : 0.f;
            ws[wi][j] = w;
            dsum += w;
        }
        __syncthreads();
#pragma unroll 2
        for (int j4 = 0; j4 < 32; j4 += 4) {
            float2 hv0 = *(float2*)&hs[j4 + 0][rn * 2];
            float2 hv1 = *(float2*)&hs[j4 + 1][rn * 2];
            float2 hv2 = *(float2*)&hs[j4 + 2][rn * 2];
            float2 hv3 = *(float2*)&hs[j4 + 3][rn * 2];
#pragma unroll
            for (int m8 = 0; m8 < 8; m8++) {
                float4 w4 = *(float4*)&ws[rm * 8 + m8][j4];
                acc[m8][0] = fmaf(w4.x, hv0.x, acc[m8][0]);
                acc[m8][1] = fmaf(w4.x, hv0.y, acc[m8][1]);
                acc[m8][0] = fmaf(w4.y, hv1.x, acc[m8][0]);
                acc[m8][1] = fmaf(w4.y, hv1.y, acc[m8][1]);
                acc[m8][0] = fmaf(w4.z, hv2.x, acc[m8][0]);
                acc[m8][1] = fmaf(w4.z, hv2.y, acc[m8][1]);
                acc[m8][0] = fmaf(w4.w, hv3.x, acc[m8][0]);
                acc[m8][1] = fmaf(w4.w, hv3.y, acc[m8][1]);
            }
        }
    }
    dpart[t >> 7][wi] = dsum;
    __syncthreads();
    if (t < 128) dinv[t] = 1.f / (dpart[0][t] + dpart[1][t]);
    __syncthreads();
#pragma unroll
    for (int m8 = 0; m8 < 8; m8++) {
        int row = rm * 8 + m8;
        float inv = dinv[row];
        float2 v;
        v.x = acc[m8][0] * inv; v.y = acc[m8][1] * inv;
        *(float2*)&out[(size_t)(i0 + row) * 128 + head * 32 + rn * 2] = v;
    }
}

// ---------------- batchnorm statistics (per column) ----------------
__global__ void k_bn_stats(const float* __restrict__ z, int C,
                           float* __restrict__ mean, float* __restrict__ rstd) {
    int c = blockIdx.x;
    double ds = 0.0, ds2 = 0.0;
    for (int r = threadIdx.x; r < NN; r += blockDim.x) {
        float v = z[(size_t)r * C + c];
        ds += v; ds2 += (double)v * v;
    }
    __shared__ double sh[256], sh2[256];
    sh[threadIdx.x] = ds; sh2[threadIdx.x] = ds2;
    __syncthreads();
    for (int o = 128; o; o >>= 1) {
        if (threadIdx.x < o) { sh[threadIdx.x] += sh[threadIdx.x + o]; sh2[threadIdx.x] += sh2[threadIdx.x + o]; }
        __syncthreads();
    }
    if (threadIdx.x == 0) {
        double mu = sh[0] / NN;
        double var = sh2[0] / NN - mu * mu;
        mean[c] = (float)mu;
        rstd[c] = rsqrtf((float)var + BN_EPS);
    }
}

// ---------------- BN apply + ELU ----------------
__global__ void k_bn_elu(const float* __restrict__ z, const float* __restrict__ mean,
                         const float* __restrict__ rstd, const float* __restrict__ gamma,
                         const float* __restrict__ beta, float* __restrict__ out, int C) {
    int idx = blockIdx.x * blockDim.x + threadIdx.x;
    int c = idx % C;
    float v = (z[idx] - mean[c]) * rstd[c] * gamma[c] + beta[c];
    out[idx] = v > 0.f ? v : (expf(v) - 1.f);
}

// ---------------- launch ----------------
extern "C" void kernel_launch(void* const* d_in, const int* in_sizes, int n_in,
                              void* d_out, int out_size) {
    const float* x   = (const float*)d_in[0];
    const int*   adj = (const int*)d_in[1];
    const float* W1  = (const float*)d_in[2];
    const float* a1s = (const float*)d_in[3];
    const float* a1d = (const float*)d_in[4];
    const float* lw1 = (const float*)d_in[5];
    const float* lb1 = (const float*)d_in[6];
    const float* g1  = (const float*)d_in[7];
    const float* be1 = (const float*)d_in[8];
    const float* W2  = (const float*)d_in[9];
    const float* a2s = (const float*)d_in[10];
    const float* a2d = (const float*)d_in[11];
    const float* lw2 = (const float*)d_in[12];
    const float* lb2 = (const float*)d_in[13];
    const float* g2  = (const float*)d_in[14];
    const float* be2 = (const float*)d_in[15];
    float* out = (float*)d_out;

    float *h1, *x1, *x2, *h2, *x3, *z4, *sc1, *sc2, *mean, *rstd;
    cudaGetSymbolAddress((void**)&h1, g_h1);
    cudaGetSymbolAddress((void**)&x1, g_x1);
    cudaGetSymbolAddress((void**)&x2, g_x2);
    cudaGetSymbolAddress((void**)&h2, g_h2);
    cudaGetSymbolAddress((void**)&x3, g_x3);
    cudaGetSymbolAddress((void**)&z4, g_z4);
    cudaGetSymbolAddress((void**)&sc1, g_sc1);
    cudaGetSymbolAddress((void**)&sc2, g_sc2);
    cudaGetSymbolAddress((void**)&mean, g_mean);
    cudaGetSymbolAddress((void**)&rstd, g_rstd);

    k_pack_mask<<<(NN * NN) / 256, 256>>>(adj);

    k_gemm_bias<128, 64, 16, 8, 4><<<dim3(512 / 64, NN / 128), 256>>>(x, W1, nullptr, h1, NN, 512, 512);

    k_attn_scores<F1><<<NN / 8, 256>>>(h1, a1s, a1d, sc1);

    k_gat1<<<dim3(NN / 64, H), 256>>>(h1, sc1, x1);

    k_gemm_bias<128, 64, 16, 8, 4><<<dim3(1, NN / 128), 256>>>(x1, lw1, lb1, x2, NN, HID1, 512);

    k_bn_stats<<<HID1, 256>>>(x2, HID1, mean, rstd);
    k_bn_elu<<<(NN * HID1) / 256, 256>>>(x2, mean, rstd, g1, be1, x2, HID1);

    k_gemm_bias<128, 64, 16, 8, 4><<<dim3(2, NN / 128), 256>>>(x2, W2, nullptr, h2, NN, 128, 64);

    k_attn_scores<F2><<<NN / 8, 256>>>(h2, a2s, a2d, sc2);

    k_gat2<<<dim3(NN / 128, H), 256>>>(h2, sc2, x3);

    k_gemm_bias<128, 16, 16, 8, 4><<<dim3(1, NN / 128), 64>>>(x3, lw2, lb2, z4, NN, OUT_F, 128);

    k_bn_stats<<<OUT_F, 256>>>(z4, OUT_F, mean, rstd);
    k_bn_elu<<<(NN * OUT_F) / 256, 256>>>(z4, mean, rstd, g2, be2, out, OUT_F);
}

// round 5
// speedup vs baseline: 2.0493x; 1.6833x over previous
#include <cuda_runtime.h>
#include <cuda_bf16.h>
#include <math.h>
#include <stdint.h>

#define NN 4096
#define NW 128
#define H 4
#define F1 128
#define F2 32
#define HN (H * NN)
#define IN_F 512
#define HID1 64
#define OUT_F 16
#define LRELU 0.2f
#define BN_EPS 1e-5f

// ---------------- scratch ----------------
__device__ float         g_h1[NN * 512];
__device__ float         g_x1[NN * 512];
__device__ float         g_x2[NN * HID1];
__device__ float         g_h2[NN * 128];
__device__ float         g_x3[NN * 128];
__device__ float         g_z4[NN * OUT_F];
__device__ float         g_sc1[6 * HN];
__device__ float         g_sc2[6 * HN];
__device__ unsigned      g_mask[NN * NW];
__device__ float         g_mean[64], g_rstd[64];
__device__ __nv_bfloat16 g_h1th[512 * NN];   // h1^T hi  [C=512][4096]
__device__ __nv_bfloat16 g_h1tl[512 * NN];   // h1^T lo
__device__ __nv_bfloat16 g_h2th[128 * NN];
__device__ __nv_bfloat16 g_h2tl[128 * NN];

// ================= helpers =================
__device__ __forceinline__ uint32_t smem_u32(const void* p) {
    uint32_t a;
    asm("{ .reg .u64 t; cvta.to.shared.u64 t, %1; cvt.u32.u64 %0, t; }" : "=r"(a) : "l"(p));
    return a;
}
__device__ __forceinline__ void cp16(uint32_t dst, const void* src) {
    asm volatile("cp.async.cg.shared.global [%0], [%1], 16;" :: "r"(dst), "l"(src));
}
__device__ __forceinline__ void cp8(uint32_t dst, const void* src) {
    asm volatile("cp.async.ca.shared.global [%0], [%1], 8;" :: "r"(dst), "l"(src));
}
#define CP_COMMIT() asm volatile("cp.async.commit_group;" ::: "memory")
#define CP_WAIT0()  asm volatile("cp.async.wait_group 0;" ::: "memory")

__device__ __forceinline__ void mma16816(float* c,
    uint32_t a0, uint32_t a1, uint32_t a2, uint32_t a3, uint32_t b0, uint32_t b1) {
    asm volatile(
        "mma.sync.aligned.m16n8k16.row.col.f32.bf16.bf16.f32 "
        "{%0,%1,%2,%3}, {%4,%5,%6,%7}, {%8,%9}, {%0,%1,%2,%3};"
        : "+f"(c[0]), "+f"(c[1]), "+f"(c[2]), "+f"(c[3])
        : "r"(a0), "r"(a1), "r"(a2), "r"(a3), "r"(b0), "r"(b1));
}
__device__ __forceinline__ void ldsm4(uint32_t& r0, uint32_t& r1, uint32_t& r2, uint32_t& r3,
                                      uint32_t addr) {
    asm volatile("ldmatrix.sync.aligned.m8n8.x4.shared.b16 {%0,%1,%2,%3}, [%4];"
                 : "=r"(r0), "=r"(r1), "=r"(r2), "=r"(r3) : "r"(addr));
}
__device__ __forceinline__ float wcalc(float es, float E, float e,
                                       float er, float Ev, float e2, unsigned bit) {
    float s = es + er;
    float v = (s > 0.f) ? E * Ev : e * e2;
    return bit ? v : 0.f;
}
__device__ __forceinline__ void packhl(float a, float b, uint32_t& hi, uint32_t& lo) {
    __nv_bfloat162 h2 = __floats2bfloat162_rn(a, b);
    hi = *(uint32_t*)&h2;
    float ra = a - __bfloat162float(h2.x);
    float rb = b - __bfloat162float(h2.y);
    __nv_bfloat162 l2 = __floats2bfloat162_rn(ra, rb);
    lo = *(uint32_t*)&l2;
}

// ---------------- adjacency -> bitmask ----------------
__global__ void k_pack_mask(const int* __restrict__ adj) {
    int gw   = (blockIdx.x * blockDim.x + threadIdx.x) >> 5;
    int lane = threadIdx.x & 31;
    int v = adj[(size_t)gw * 32 + lane];
    unsigned m = __ballot_sync(0xffffffffu, v > 0);
    if (lane == 0) g_mask[gw] = m;
}

// ---------------- generic tiled fp32 GEMM (+ optional bias) ----------------
template <int BM, int BN, int BK, int TM, int TN>
__global__ void k_gemm_bias(const float* __restrict__ A, const float* __restrict__ B,
                            const float* __restrict__ bias, float* __restrict__ C,
                            int M, int Nn, int K) {
    constexpr int THREADS = (BM / TM) * (BN / TN);
    __shared__ float As[BM][BK + 1];
    __shared__ float Bs[BK][BN + 1];
    int tid = threadIdx.x;
    int rm = tid / (BN / TN);
    int rn = tid % (BN / TN);
    int m0 = blockIdx.y * BM, n0 = blockIdx.x * BN;
    float acc[TM][TN];
#pragma unroll
    for (int m = 0; m < TM; m++)
#pragma unroll
        for (int n = 0; n < TN; n++) acc[m][n] = 0.f;

    for (int k0 = 0; k0 < K; k0 += BK) {
        for (int idx = tid; idx < BM * BK; idx += THREADS) {
            int r = idx / BK, c = idx % BK;
            As[r][c] = A[(size_t)(m0 + r) * K + k0 + c];
        }
        for (int idx = tid; idx < BK * BN; idx += THREADS) {
            int r = idx / BN, c = idx % BN;
            Bs[r][c] = B[(size_t)(k0 + r) * Nn + n0 + c];
        }
        __syncthreads();
#pragma unroll
        for (int kk = 0; kk < BK; kk++) {
            float a[TM], b[TN];
#pragma unroll
            for (int m = 0; m < TM; m++) a[m] = As[rm * TM + m][kk];
#pragma unroll
            for (int n = 0; n < TN; n++) b[n] = Bs[kk][rn * TN + n];
#pragma unroll
            for (int m = 0; m < TM; m++)
#pragma unroll
                for (int n = 0; n < TN; n++) acc[m][n] = fmaf(a[m], b[n], acc[m][n]);
        }
        __syncthreads();
    }
#pragma unroll
    for (int m = 0; m < TM; m++) {
        int row = m0 + rm * TM + m;
#pragma unroll
        for (int n = 0; n < TN; n++) {
            int col = n0 + rn * TN + n;
            float v = acc[m][n];
            if (bias) v += bias[col];
            C[(size_t)row * Nn + col] = v;
        }
    }
}

// ---------------- per-node scores + precomputed exps ----------------
template <int F>
__global__ void k_attn_scores(const float* __restrict__ hfeat,
                              const float* __restrict__ a_src,
                              const float* __restrict__ a_dst,
                              float* __restrict__ sc) {
    int n = blockIdx.x * (blockDim.x >> 5) + (threadIdx.x >> 5);
    int lane = threadIdx.x & 31;
    if (n >= NN) return;
    const float* row = hfeat + (size_t)n * (H * F);
#pragma unroll
    for (int h = 0; h < H; h++) {
        float ss = 0.f, sd = 0.f;
        for (int k = lane; k < F; k += 32) {
            float v = row[h * F + k];
            ss = fmaf(v, a_src[h * F + k], ss);
            sd = fmaf(v, a_dst[h * F + k], sd);
        }
#pragma unroll
        for (int o = 16; o; o >>= 1) {
            ss += __shfl_xor_sync(0xffffffffu, ss, o);
            sd += __shfl_xor_sync(0xffffffffu, sd, o);
        }
        if (lane == 0) {
            int idx = h * NN + n;
            sc[0 * HN + idx] = ss;
            sc[1 * HN + idx] = expf(ss);
            sc[2 * HN + idx] = expf(LRELU * ss);
            sc[3 * HN + idx] = sd;
            sc[4 * HN + idx] = expf(sd);
            sc[5 * HN + idx] = expf(LRELU * sd);
        }
    }
}

// ---------------- transpose fp32 [R,C] -> bf16 hi/lo [C,R] ----------------
__global__ void k_transpose_split(const float* __restrict__ in,
                                  __nv_bfloat16* __restrict__ oh,
                                  __nv_bfloat16* __restrict__ ol, int R, int C) {
    __shared__ float tile[32][33];
    int r0 = blockIdx.x * 32, c0 = blockIdx.y * 32;
    int tx = threadIdx.x, ty = threadIdx.y;  // 32 x 8
#pragma unroll
    for (int q = 0; q < 4; q++)
        tile[ty * 4 + q][tx] = in[(size_t)(r0 + ty * 4 + q) * C + c0 + tx];
    __syncthreads();
#pragma unroll
    for (int q = 0; q < 4; q++) {
        float v = tile[tx][ty * 4 + q];
        __nv_bfloat16 hi = __float2bfloat16(v);
        float lo = v - __bfloat162float(hi);
        size_t o = (size_t)(c0 + ty * 4 + q) * R + r0 + tx;
        oh[o] = hi;
        ol[o] = __float2bfloat16(lo);
    }
}

// ================ GAT aggregation via split-bf16 mma.sync ================
// CTA: 128 i-rows x one head, 8 warps. Warp = 32 rows (rb) x F/2 cols (ch).
// A (weights) generated into fragments as hi+lo bf16 pairs; B (hT) hi+lo tiles
// double-buffered via cp.async, fragments fetched with ldmatrix.x4.
template <int F>
__device__ __forceinline__ void load_chunk(int t, int head, int i0, int c, int buf,
                                           char* BtB, unsigned* mk, float* edb,
                                           const __nv_bfloat16* hTh,
                                           const __nv_bfloat16* hTl,
                                           const float* sc) {
    constexpr int BT = F * 128;
    char* dsthi = BtB + buf * 2 * BT;
    char* dstlo = dsthi + BT;
    for (int idx = t; idx < F * 8; idx += 256) {
        int f = idx >> 3, q = idx & 7;
        uint32_t off = (uint32_t)(f * 128 + (((q ^ (f & 7)) << 4)));
        size_t src = (size_t)(head * F + f) * NN + c * 64 + q * 8;
        cp16(smem_u32(dsthi + off), hTh + src);
        cp16(smem_u32(dstlo + off), hTl + src);
    }
    if (t < 128) cp8(smem_u32(mk + buf * 256 + t * 2), &g_mask[(size_t)(i0 + t) * NW + c * 2]);
    if (t < 48) {
        int a = t >> 4, q = t & 15;
        cp16(smem_u32(edb + buf * 192 + a * 64 + q * 4),
             &sc[(size_t)(3 + a) * HN + head * NN + c * 64 + q * 4]);
    }
}

template <int F>
__global__ __launch_bounds__(256) void k_gat_hmma(const __nv_bfloat16* __restrict__ hTh,
                                                  const __nv_bfloat16* __restrict__ hTl,
                                                  const float* __restrict__ sc,
                                                  float* __restrict__ out) {
    constexpr int BT = F * 128;
    constexpr int MP = F / 32;         // ldmatrix.x4 calls per ks per col-half
    extern __shared__ char smem[];
    char* BtB = smem;                                   // [2][2][BT]
    unsigned* mk = (unsigned*)(smem + 4 * BT);          // [2][256]
    float* edb = (float*)(smem + 4 * BT + 2048);        // [2][192]
    float* dsh = (float*)(smem + 4 * BT + 3584);        // [128]
    float* dis = dsh + 128;

    int t = threadIdx.x, wid = t >> 5, lane = t & 31;
    int g = lane >> 2, tig = lane & 3;
    int rb = wid & 3, ch = wid >> 2;
    int head = blockIdx.y, i0 = blockIdx.x * 128;
    uint32_t sb = smem_u32(smem);

    int r00 = rb * 32 + g, r01 = r00 + 8, r10 = r00 + 16, r11 = r00 + 24;
    const float* scb = sc + head * NN + i0;
    float es00 = scb[r00], E00 = scb[HN + r00], e00 = scb[2 * HN + r00];
    float es01 = scb[r01], E01 = scb[HN + r01], e01 = scb[2 * HN + r01];
    float es10 = scb[r10], E10 = scb[HN + r10], e10 = scb[2 * HN + r10];
    float es11 = scb[r11], E11 = scb[HN + r11], e11 = scb[2 * HN + r11];

    // ldmatrix lane geometry (constant per thread)
    int flr = ((lane >> 4) & 1) * 8 + (lane & 7);
    int qb = (lane >> 3) & 1;
    int sxw = flr & 7;
    uint32_t fcol = (uint32_t)((ch * (F / 2) + flr) * 128);

    float acc[2][2 * MP][4];
#pragma unroll
    for (int rt = 0; rt < 2; rt++)
#pragma unroll
        for (int nt = 0; nt < 2 * MP; nt++)
#pragma unroll
            for (int q = 0; q < 4; q++) acc[rt][nt][q] = 0.f;
    float d00 = 0.f, d01 = 0.f, d10 = 0.f, d11 = 0.f;

    load_chunk<F>(t, head, i0, 0, 0, BtB, mk, edb, hTh, hTl, sc);
    CP_COMMIT();

    for (int c = 0; c < 64; c++) {
        int b = c & 1;
        CP_WAIT0();
        __syncthreads();
        if (c < 63) {
            load_chunk<F>(t, head, i0, c + 1, b ^ 1, BtB, mk, edb, hTh, hTl, sc);
            CP_COMMIT();
        }
        unsigned* mkb = mk + b * 256;
        unsigned w00A = mkb[r00 * 2], w00B = mkb[r00 * 2 + 1];
        unsigned w01A = mkb[r01 * 2], w01B = mkb[r01 * 2 + 1];
        unsigned w10A = mkb[r10 * 2], w10B = mkb[r10 * 2 + 1];
        unsigned w11A = mkb[r11 * 2], w11B = mkb[r11 * 2 + 1];
        float* ed = edb + b * 192;
        uint32_t bufbase = sb + (uint32_t)(b * 2 * BT);
#pragma unroll
        for (int ks = 0; ks < 4; ks++) {
            int jb = ks * 16 + tig * 2;
            float2 erL = *(float2*)&ed[jb];
            float2 erH = *(float2*)&ed[jb + 8];
            float2 EvL = *(float2*)&ed[64 + jb];
            float2 EvH = *(float2*)&ed[64 + jb + 8];
            float2 e2L = *(float2*)&ed[128 + jb];
            float2 e2H = *(float2*)&ed[128 + jb + 8];
            int bit = (ks & 1) * 16 + tig * 2;
            unsigned w00 = (ks < 2) ? w00A : w00B;
            unsigned w01 = (ks < 2) ? w01A : w01B;
            unsigned w10 = (ks < 2) ? w10A : w10B;
            unsigned w11 = (ks < 2) ? w11A : w11B;

            uint32_t Ah[2][4], Al[2][4];
            {
                float a0 = wcalc(es00, E00, e00, erL.x, EvL.x, e2L.x, (w00 >> bit) & 1u);
                float a1 = wcalc(es00, E00, e00, erL.y, EvL.y, e2L.y, (w00 >> (bit + 1)) & 1u);
                float a2 = wcalc(es00, E00, e00, erH.x, EvH.x, e2H.x, (w00 >> (bit + 8)) & 1u);
                float a3 = wcalc(es00, E00, e00, erH.y, EvH.y, e2H.y, (w00 >> (bit + 9)) & 1u);
                float b0 = wcalc(es01, E01, e01, erL.x, EvL.x, e2L.x, (w01 >> bit) & 1u);
                float b1 = wcalc(es01, E01, e01, erL.y, EvL.y, e2L.y, (w01 >> (bit + 1)) & 1u);
                float b2 = wcalc(es01, E01, e01, erH.x, EvH.x, e2H.x, (w01 >> (bit + 8)) & 1u);
                float b3 = wcalc(es01, E01, e01, erH.y, EvH.y, e2H.y, (w01 >> (bit + 9)) & 1u);
                d00 += a0 + a1 + a2 + a3;
                d01 += b0 + b1 + b2 + b3;
                packhl(a0, a1, Ah[0][0], Al[0][0]);
                packhl(b0, b1, Ah[0][1], Al[0][1]);
                packhl(a2, a3, Ah[0][2], Al[0][2]);
                packhl(b2, b3, Ah[0][3], Al[0][3]);
            }
            {
                float a0 = wcalc(es10, E10, e10, erL.x, EvL.x, e2L.x, (w10 >> bit) & 1u);
                float a1 = wcalc(es10, E10, e10, erL.y, EvL.y, e2L.y, (w10 >> (bit + 1)) & 1u);
                float a2 = wcalc(es10, E10, e10, erH.x, EvH.x, e2H.x, (w10 >> (bit + 8)) & 1u);
                float a3 = wcalc(es10, E10, e10, erH.y, EvH.y, e2H.y, (w10 >> (bit + 9)) & 1u);
                float b0 = wcalc(es11, E11, e11, erL.x, EvL.x, e2L.x, (w11 >> bit) & 1u);
                float b1 = wcalc(es11, E11, e11, erL.y, EvL.y, e2L.y, (w11 >> (bit + 1)) & 1u);
                float b2 = wcalc(es11, E11, e11, erH.x, EvH.x, e2H.x, (w11 >> (bit + 8)) & 1u);
                float b3 = wcalc(es11, E11, e11, erH.y, EvH.y, e2H.y, (w11 >> (bit + 9)) & 1u);
                d10 += a0 + a1 + a2 + a3;
                d11 += b0 + b1 + b2 + b3;
                packhl(a0, a1, Ah[1][0], Al[1][0]);
                packhl(b0, b1, Ah[1][1], Al[1][1]);
                packhl(a2, a3, Ah[1][2], Al[1][2]);
                packhl(b2, b3, Ah[1][3], Al[1][3]);
            }
            uint32_t swz = (uint32_t)((((2 * ks + qb) ^ sxw) << 4));
#pragma unroll
            for (int mp = 0; mp < MP; mp++) {
                uint32_t ah = bufbase + fcol + (uint32_t)(mp * 2048) + swz;
                uint32_t al = ah + BT;
                uint32_t bh0, bh1, bh2, bh3, bl0, bl1, bl2, bl3;
                ldsm4(bh0, bh1, bh2, bh3, ah);
                ldsm4(bl0, bl1, bl2, bl3, al);
#pragma unroll
                for (int rt = 0; rt < 2; rt++) {
                    float* c0 = acc[rt][2 * mp];
                    float* c1 = acc[rt][2 * mp + 1];
                    mma16816(c0, Ah[rt][0], Ah[rt][1], Ah[rt][2], Ah[rt][3], bh0, bh1);
                    mma16816(c0, Ah[rt][0], Ah[rt][1], Ah[rt][2], Ah[rt][3], bl0, bl1);
                    mma16816(c0, Al[rt][0], Al[rt][1], Al[rt][2], Al[rt][3], bh0, bh1);
                    mma16816(c1, Ah[rt][0], Ah[rt][1], Ah[rt][2], Ah[rt][3], bh2, bh3);
                    mma16816(c1, Ah[rt][0], Ah[rt][1], Ah[rt][2], Ah[rt][3], bl2, bl3);
                    mma16816(c1, Al[rt][0], Al[rt][1], Al[rt][2], Al[rt][3], bh2, bh3);
                }
            }
        }
    }
    // denominator: reduce across tig lanes, ch==0 warps write
    d00 += __shfl_xor_sync(0xffffffffu, d00, 1);
    d00 += __shfl_xor_sync(0xffffffffu, d00, 2);
    d01 += __shfl_xor_sync(0xffffffffu, d01, 1);
    d01 += __shfl_xor_sync(0xffffffffu, d01, 2);
    d10 += __shfl_xor_sync(0xffffffffu, d10, 1);
    d10 += __shfl_xor_sync(0xffffffffu, d10, 2);
    d11 += __shfl_xor_sync(0xffffffffu, d11, 1);
    d11 += __shfl_xor_sync(0xffffffffu, d11, 2);
    if (ch == 0 && tig == 0) {
        dsh[r00] = d00; dsh[r01] = d01; dsh[r10] = d10; dsh[r11] = d11;
    }
    __syncthreads();
    if (t < 128) dis[t] = 1.f / dsh[t];
    __syncthreads();
#pragma unroll
    for (int rt = 0; rt < 2; rt++) {
        int row = rb * 32 + rt * 16 + g;
        float iv0 = dis[row], iv1 = dis[row + 8];
#pragma unroll
        for (int nt = 0; nt < 2 * MP; nt++) {
            int col = head * F + ch * (F / 2) + nt * 8 + tig * 2;
            float2 v0 = make_float2(acc[rt][nt][0] * iv0, acc[rt][nt][1] * iv0);
            float2 v1 = make_float2(acc[rt][nt][2] * iv1, acc[rt][nt][3] * iv1);
            *(float2*)&out[(size_t)(i0 + row) * (H * F) + col] = v0;
            *(float2*)&out[(size_t)(i0 + row + 8) * (H * F) + col] = v1;
        }
    }
}

// ---------------- batchnorm statistics ----------------
__global__ void k_bn_stats(const float* __restrict__ z, int C,
                           float* __restrict__ mean, float* __restrict__ rstd) {
    int c = blockIdx.x;
    double ds = 0.0, ds2 = 0.0;
    for (int r = threadIdx.x; r < NN; r += blockDim.x) {
        float v = z[(size_t)r * C + c];
        ds += v; ds2 += (double)v * v;
    }
    __shared__ double sh[256], sh2[256];
    sh[threadIdx.x] = ds; sh2[threadIdx.x] = ds2;
    __syncthreads();
    for (int o = 128; o; o >>= 1) {
        if (threadIdx.x < o) { sh[threadIdx.x] += sh[threadIdx.x + o]; sh2[threadIdx.x] += sh2[threadIdx.x + o]; }
        __syncthreads();
    }
    if (threadIdx.x == 0) {
        double mu = sh[0] / NN;
        double var = sh2[0] / NN - mu * mu;
        mean[c] = (float)mu;
        rstd[c] = rsqrtf((float)var + BN_EPS);
    }
}

__global__ void k_bn_elu(const float* __restrict__ z, const float* __restrict__ mean,
                         const float* __restrict__ rstd, const float* __restrict__ gamma,
                         const float* __restrict__ beta, float* __restrict__ out, int C) {
    int idx = blockIdx.x * blockDim.x + threadIdx.x;
    int c = idx % C;
    float v = (z[idx] - mean[c]) * rstd[c] * gamma[c] + beta[c];
    out[idx] = v > 0.f ? v : (expf(v) - 1.f);
}

// ---------------- launch ----------------
extern "C" void kernel_launch(void* const* d_in, const int* in_sizes, int n_in,
                              void* d_out, int out_size) {
    const float* x   = (const float*)d_in[0];
    const int*   adj = (const int*)d_in[1];
    const float* W1  = (const float*)d_in[2];
    const float* a1s = (const float*)d_in[3];
    const float* a1d = (const float*)d_in[4];
    const float* lw1 = (const float*)d_in[5];
    const float* lb1 = (const float*)d_in[6];
    const float* g1  = (const float*)d_in[7];
    const float* be1 = (const float*)d_in[8];
    const float* W2  = (const float*)d_in[9];
    const float* a2s = (const float*)d_in[10];
    const float* a2d = (const float*)d_in[11];
    const float* lw2 = (const float*)d_in[12];
    const float* lb2 = (const float*)d_in[13];
    const float* g2  = (const float*)d_in[14];
    const float* be2 = (const float*)d_in[15];
    float* out = (float*)d_out;

    float *h1, *x1, *x2, *h2, *x3, *z4, *sc1, *sc2, *mean, *rstd;
    __nv_bfloat16 *h1th, *h1tl, *h2th, *h2tl;
    cudaGetSymbolAddress((void**)&h1, g_h1);
    cudaGetSymbolAddress((void**)&x1, g_x1);
    cudaGetSymbolAddress((void**)&x2, g_x2);
    cudaGetSymbolAddress((void**)&h2, g_h2);
    cudaGetSymbolAddress((void**)&x3, g_x3);
    cudaGetSymbolAddress((void**)&z4, g_z4);
    cudaGetSymbolAddress((void**)&sc1, g_sc1);
    cudaGetSymbolAddress((void**)&sc2, g_sc2);
    cudaGetSymbolAddress((void**)&mean, g_mean);
    cudaGetSymbolAddress((void**)&rstd, g_rstd);
    cudaGetSymbolAddress((void**)&h1th, g_h1th);
    cudaGetSymbolAddress((void**)&h1tl, g_h1tl);
    cudaGetSymbolAddress((void**)&h2th, g_h2th);
    cudaGetSymbolAddress((void**)&h2tl, g_h2tl);

    const int SMEM1 = 4 * F1 * 128 + 3584 + 1024;   // 70144
    const int SMEM2 = 4 * F2 * 128 + 3584 + 1024;   // 20992
    cudaFuncSetAttribute(k_gat_hmma<F1>, cudaFuncAttributeMaxDynamicSharedMemorySize, SMEM1);
    cudaFuncSetAttribute(k_gat_hmma<F2>, cudaFuncAttributeMaxDynamicSharedMemorySize, SMEM2);

    k_pack_mask<<<(NN * NN) / 256, 256>>>(adj);

    k_gemm_bias<128, 64, 16, 8, 4><<<dim3(512 / 64, NN / 128), 256>>>(x, W1, nullptr, h1, NN, 512, 512);

    k_attn_scores<F1><<<NN / 8, 256>>>(h1, a1s, a1d, sc1);
    k_transpose_split<<<dim3(NN / 32, 512 / 32), dim3(32, 8)>>>(h1, h1th, h1tl, NN, 512);

    k_gat_hmma<F1><<<dim3(NN / 128, H), 256, SMEM1>>>(h1th, h1tl, sc1, x1);

    k_gemm_bias<128, 64, 16, 8, 4><<<dim3(1, NN / 128), 256>>>(x1, lw1, lb1, x2, NN, HID1, 512);

    k_bn_stats<<<HID1, 256>>>(x2, HID1, mean, rstd);
    k_bn_elu<<<(NN * HID1) / 256, 256>>>(x2, mean, rstd, g1, be1, x2, HID1);

    k_gemm_bias<128, 64, 16, 8, 4><<<dim3(2, NN / 128), 256>>>(x2, W2, nullptr, h2, NN, 128, 64);

    k_attn_scores<F2><<<NN / 8, 256>>>(h2, a2s, a2d, sc2);
    k_transpose_split<<<dim3(NN / 32, 128 / 32), dim3(32, 8)>>>(h2, h2th, h2tl, NN, 128);

    k_gat_hmma<F2><<<dim3(NN / 128, H), 256, SMEM2>>>(h2th, h2tl, sc2, x3);

    k_gemm_bias<128, 16, 16, 8, 4><<<dim3(1, NN / 128), 64>>>(x3, lw2, lb2, z4, NN, OUT_F, 128);

    k_bn_stats<<<OUT_F, 256>>>(z4, OUT_F, mean, rstd);
    k_bn_elu<<<(NN * OUT_F) / 256, 256>>>(z4, mean, rstd, g2, be2, out, OUT_F);
}

// round 6
// speedup vs baseline: 3.2883x; 1.6046x over previous
#include <cuda_runtime.h>
#include <cuda_bf16.h>
#include <math.h>
#include <stdint.h>

#define NN 4096
#define NW 128
#define H 4
#define F1 128
#define F2 32
#define HN (H * NN)
#define IN_F 512
#define HID1 64
#define OUT_F 16
#define LRELU 0.2f
#define BN_EPS 1e-5f

// ---------------- scratch ----------------
__device__ float         g_h1[NN * 512];
__device__ float         g_x1[NN * 512];
__device__ float         g_x2[NN * HID1];
__device__ float         g_h2[NN * 128];
__device__ float         g_x3[NN * 128];
__device__ float         g_z4[NN * OUT_F];
__device__ float         g_sc1[6 * HN];
__device__ float         g_sc2[6 * HN];
__device__ unsigned      g_mask[NN * NW];
__device__ float         g_mean[64], g_rstd[64];
__device__ float         g_bnpart[32 * 2 * 64];
__device__ __nv_bfloat16 g_h1th[512 * NN];
__device__ __nv_bfloat16 g_h1tl[512 * NN];
__device__ __nv_bfloat16 g_h2th[128 * NN];
__device__ __nv_bfloat16 g_h2tl[128 * NN];
__device__ __nv_bfloat16 g_ah[NN * 512];    // A operand hi (x / x1 / x2 reused)
__device__ __nv_bfloat16 g_al[NN * 512];    // A operand lo
__device__ __nv_bfloat16 g_wth[512 * 512];  // W^T hi [N][K]
__device__ __nv_bfloat16 g_wtl[512 * 512];  // W^T lo

// ================= helpers =================
__device__ __forceinline__ uint32_t smem_u32(const void* p) {
    uint32_t a;
    asm("{ .reg .u64 t; cvta.to.shared.u64 t, %1; cvt.u32.u64 %0, t; }" : "=r"(a) : "l"(p));
    return a;
}
__device__ __forceinline__ void cp16(uint32_t dst, const void* src) {
    asm volatile("cp.async.cg.shared.global [%0], [%1], 16;" :: "r"(dst), "l"(src));
}
__device__ __forceinline__ void cp8(uint32_t dst, const void* src) {
    asm volatile("cp.async.ca.shared.global [%0], [%1], 8;" :: "r"(dst), "l"(src));
}
#define CP_COMMIT() asm volatile("cp.async.commit_group;" ::: "memory")
#define CP_WAIT0()  asm volatile("cp.async.wait_group 0;" ::: "memory")

__device__ __forceinline__ void mma16816(float* c,
    uint32_t a0, uint32_t a1, uint32_t a2, uint32_t a3, uint32_t b0, uint32_t b1) {
    asm volatile(
        "mma.sync.aligned.m16n8k16.row.col.f32.bf16.bf16.f32 "
        "{%0,%1,%2,%3}, {%4,%5,%6,%7}, {%8,%9}, {%0,%1,%2,%3};"
        : "+f"(c[0]), "+f"(c[1]), "+f"(c[2]), "+f"(c[3])
        : "r"(a0), "r"(a1), "r"(a2), "r"(a3), "r"(b0), "r"(b1));
}
__device__ __forceinline__ void ldsm4(uint32_t& r0, uint32_t& r1, uint32_t& r2, uint32_t& r3,
                                      uint32_t addr) {
    asm volatile("ldmatrix.sync.aligned.m8n8.x4.shared.b16 {%0,%1,%2,%3}, [%4];"
                 : "=r"(r0), "=r"(r1), "=r"(r2), "=r"(r3) : "r"(addr));
}
__device__ __forceinline__ float wcalc(float es, float E, float e,
                                       float er, float Ev, float e2, unsigned bit) {
    float s = es + er;
    float v = (s > 0.f) ? E * Ev : e * e2;
    return bit ? v : 0.f;
}
__device__ __forceinline__ void packhl(float a, float b, uint32_t& hi, uint32_t& lo) {
    __nv_bfloat162 h2 = __floats2bfloat162_rn(a, b);
    hi = *(uint32_t*)&h2;
    float ra = a - __bfloat162float(h2.x);
    float rb = b - __bfloat162float(h2.y);
    __nv_bfloat162 l2 = __floats2bfloat162_rn(ra, rb);
    lo = *(uint32_t*)&l2;
}

// ---------------- adjacency -> bitmask ----------------
__global__ void k_pack_mask(const int* __restrict__ adj) {
    int gw   = (blockIdx.x * blockDim.x + threadIdx.x) >> 5;
    int lane = threadIdx.x & 31;
    int v = adj[(size_t)gw * 32 + lane];
    unsigned m = __ballot_sync(0xffffffffu, v > 0);
    if (lane == 0) g_mask[gw] = m;
}

// ---------------- elementwise fp32 -> bf16 hi/lo split ----------------
__global__ void k_split_bf16(const float* __restrict__ in,
                             __nv_bfloat16* __restrict__ oh,
                             __nv_bfloat16* __restrict__ ol) {
    int idx = blockIdx.x * blockDim.x + threadIdx.x;
    float4 v = ((const float4*)in)[idx];
    __nv_bfloat162 h0 = __floats2bfloat162_rn(v.x, v.y);
    __nv_bfloat162 h1 = __floats2bfloat162_rn(v.z, v.w);
    __nv_bfloat162 l0 = __floats2bfloat162_rn(v.x - __bfloat162float(h0.x),
                                              v.y - __bfloat162float(h0.y));
    __nv_bfloat162 l1 = __floats2bfloat162_rn(v.z - __bfloat162float(h1.x),
                                              v.w - __bfloat162float(h1.y));
    ((__nv_bfloat162*)oh)[idx * 2] = h0;
    ((__nv_bfloat162*)oh)[idx * 2 + 1] = h1;
    ((__nv_bfloat162*)ol)[idx * 2] = l0;
    ((__nv_bfloat162*)ol)[idx * 2 + 1] = l1;
}

// ---------------- transpose fp32 [R,C] -> bf16 hi/lo [C,R] ----------------
__global__ void k_transpose_split(const float* __restrict__ in,
                                  __nv_bfloat16* __restrict__ oh,
                                  __nv_bfloat16* __restrict__ ol, int R, int C) {
    __shared__ float tile[32][33];
    int r0 = blockIdx.x * 32, c0 = blockIdx.y * 32;
    int tx = threadIdx.x, ty = threadIdx.y;  // 32 x 8
#pragma unroll
    for (int q = 0; q < 4; q++)
        tile[ty * 4 + q][tx] = in[(size_t)(r0 + ty * 4 + q) * C + c0 + tx];
    __syncthreads();
#pragma unroll
    for (int q = 0; q < 4; q++) {
        float v = tile[tx][ty * 4 + q];
        __nv_bfloat16 hi = __float2bfloat16(v);
        float lo = v - __bfloat162float(hi);
        size_t o = (size_t)(c0 + ty * 4 + q) * R + r0 + tx;
        oh[o] = hi;
        ol[o] = __float2bfloat16(lo);
    }
}

// ================ split-bf16 HMMA GEMM ================
// C[M,Ntot](fp32) = A[M,K] @ B^T (B stored [N][K]) + bias.
// BM=128, BN=64, BK=64. 8 warps: 4 m-warps x 2 n-warps, warp tile 32x32.
// smem/buf: Ahi 16K | Alo 16K | Bhi 8K | Blo 8K = 48K; double buffered = 96K.
#define GB_BUF 49152

__device__ __forceinline__ void gemm_load(int t, int m0, int n0, int c, int buf,
                                          uint32_t sb, int K,
                                          const __nv_bfloat16* Ah, const __nv_bfloat16* Al,
                                          const __nv_bfloat16* Bh, const __nv_bfloat16* Bl) {
    uint32_t base = sb + buf * GB_BUF;
#pragma unroll
    for (int idx = t; idx < 1024; idx += 256) {
        int m = idx >> 3, q = idx & 7;
        uint32_t off = base + (uint32_t)(m * 128 + ((q ^ (m & 7)) << 4));
        size_t src = (size_t)(m0 + m) * K + c * 64 + q * 8;
        cp16(off, Ah + src);
        cp16(off + 16384, Al + src);
    }
#pragma unroll
    for (int idx = t; idx < 512; idx += 256) {
        int n = idx >> 3, q = idx & 7;
        uint32_t off = base + 32768 + (uint32_t)(n * 128 + ((q ^ (n & 7)) << 4));
        size_t src = (size_t)(n0 + n) * K + c * 64 + q * 8;
        cp16(off, Bh + src);
        cp16(off + 8192, Bl + src);
    }
}

__global__ __launch_bounds__(256) void k_gemm_hmma(
    const __nv_bfloat16* __restrict__ Ah, const __nv_bfloat16* __restrict__ Al,
    const __nv_bfloat16* __restrict__ Bh, const __nv_bfloat16* __restrict__ Bl,
    const float* __restrict__ bias, float* __restrict__ C, int K, int Ntot) {
    extern __shared__ char sm[];
    uint32_t sb = smem_u32(sm);
    int t = threadIdx.x, wid = t >> 5, lane = t & 31;
    int m0 = blockIdx.x * 128, n0 = blockIdx.y * 64;
    int wm = (wid & 3) * 32, wn = (wid >> 2) * 32;
    int g = lane >> 2, tig = lane & 3;
    int nc = K >> 6;

    int arow = (lane & 7) + ((lane >> 3) & 1) * 8;
    int ahalf = lane >> 4;
    int brow = ((lane >> 4) << 3) + (lane & 7);
    int bhalf = (lane >> 3) & 1;

    float acc[2][4][4];
#pragma unroll
    for (int mt = 0; mt < 2; mt++)
#pragma unroll
        for (int nt = 0; nt < 4; nt++)
#pragma unroll
            for (int q = 0; q < 4; q++) acc[mt][nt][q] = 0.f;

    gemm_load(t, m0, n0, 0, 0, sb, K, Ah, Al, Bh, Bl);
    CP_COMMIT();

    for (int c = 0; c < nc; c++) {
        int buf = c & 1;
        CP_WAIT0();
        __syncthreads();
        if (c + 1 < nc) {
            gemm_load(t, m0, n0, c + 1, buf ^ 1, sb, K, Ah, Al, Bh, Bl);
            CP_COMMIT();
        }
        uint32_t base = sb + buf * GB_BUF;
#pragma unroll
        for (int ks = 0; ks < 4; ks++) {
            uint32_t ahf[2][4], alf[2][4], bhf[2][4], blf[2][4];
#pragma unroll
            for (int mt = 0; mt < 2; mt++) {
                int r = wm + mt * 16 + arow;
                int slot = 2 * ks + ahalf;
                uint32_t ad = base + (uint32_t)(r * 128 + ((slot ^ (r & 7)) << 4));
                ldsm4(ahf[mt][0], ahf[mt][1], ahf[mt][2], ahf[mt][3], ad);
                ldsm4(alf[mt][0], alf[mt][1], alf[mt][2], alf[mt][3], ad + 16384);
            }
#pragma unroll
            for (int np = 0; np < 2; np++) {
                int r = wn + np * 16 + brow;
                int slot = 2 * ks + bhalf;
                uint32_t bd = base + 32768 + (uint32_t)(r * 128 + ((slot ^ (r & 7)) << 4));
                ldsm4(bhf[np][0], bhf[np][1], bhf[np][2], bhf[np][3], bd);
                ldsm4(blf[np][0], blf[np][1], blf[np][2], blf[np][3], bd + 8192);
            }
#pragma unroll
            for (int mt = 0; mt < 2; mt++)
#pragma unroll
                for (int nt = 0; nt < 4; nt++) {
                    int np = nt >> 1, sel = (nt & 1) * 2;
                    uint32_t bh0 = bhf[np][sel], bh1 = bhf[np][sel + 1];
                    uint32_t bl0 = blf[np][sel], bl1 = blf[np][sel + 1];
                    float* cacc = acc[mt][nt];
                    mma16816(cacc, ahf[mt][0], ahf[mt][1], ahf[mt][2], ahf[mt][3], bh0, bh1);
                    mma16816(cacc, ahf[mt][0], ahf[mt][1], ahf[mt][2], ahf[mt][3], bl0, bl1);
                    mma16816(cacc, alf[mt][0], alf[mt][1], alf[mt][2], alf[mt][3], bh0, bh1);
                }
        }
    }
#pragma unroll
    for (int mt = 0; mt < 2; mt++)
#pragma unroll
        for (int nt = 0; nt < 4; nt++) {
            int row = m0 + wm + mt * 16 + g;
            int col = n0 + wn + nt * 8 + tig * 2;
            float bv0 = bias ? bias[col] : 0.f;
            float bv1 = bias ? bias[col + 1] : 0.f;
            float2 v0 = make_float2(acc[mt][nt][0] + bv0, acc[mt][nt][1] + bv1);
            float2 v1 = make_float2(acc[mt][nt][2] + bv0, acc[mt][nt][3] + bv1);
            *(float2*)&C[(size_t)row * Ntot + col] = v0;
            *(float2*)&C[(size_t)(row + 8) * Ntot + col] = v1;
        }
}

// ---------------- generic tiled fp32 GEMM (+ optional bias), for lin2 ----------------
template <int BM, int BN, int BK, int TM, int TN>
__global__ void k_gemm_bias(const float* __restrict__ A, const float* __restrict__ B,
                            const float* __restrict__ bias, float* __restrict__ C,
                            int M, int Nn, int K) {
    constexpr int THREADS = (BM / TM) * (BN / TN);
    __shared__ float As[BM][BK + 1];
    __shared__ float Bs[BK][BN + 1];
    int tid = threadIdx.x;
    int rm = tid / (BN / TN);
    int rn = tid % (BN / TN);
    int m0 = blockIdx.y * BM, n0 = blockIdx.x * BN;
    float acc[TM][TN];
#pragma unroll
    for (int m = 0; m < TM; m++)
#pragma unroll
        for (int n = 0; n < TN; n++) acc[m][n] = 0.f;

    for (int k0 = 0; k0 < K; k0 += BK) {
        for (int idx = tid; idx < BM * BK; idx += THREADS) {
            int r = idx / BK, c = idx % BK;
            As[r][c] = A[(size_t)(m0 + r) * K + k0 + c];
        }
        for (int idx = tid; idx < BK * BN; idx += THREADS) {
            int r = idx / BN, c = idx % BN;
            Bs[r][c] = B[(size_t)(k0 + r) * Nn + n0 + c];
        }
        __syncthreads();
#pragma unroll
        for (int kk = 0; kk < BK; kk++) {
            float a[TM], b[TN];
#pragma unroll
            for (int m = 0; m < TM; m++) a[m] = As[rm * TM + m][kk];
#pragma unroll
            for (int n = 0; n < TN; n++) b[n] = Bs[kk][rn * TN + n];
#pragma unroll
            for (int m = 0; m < TM; m++)
#pragma unroll
                for (int n = 0; n < TN; n++) acc[m][n] = fmaf(a[m], b[n], acc[m][n]);
        }
        __syncthreads();
    }
#pragma unroll
    for (int m = 0; m < TM; m++) {
        int row = m0 + rm * TM + m;
#pragma unroll
        for (int n = 0; n < TN; n++) {
            int col = n0 + rn * TN + n;
            float v = acc[m][n];
            if (bias) v += bias[col];
            C[(size_t)row * Nn + col] = v;
        }
    }
}

// ---------------- per-node scores + precomputed exps ----------------
template <int F>
__global__ void k_attn_scores(const float* __restrict__ hfeat,
                              const float* __restrict__ a_src,
                              const float* __restrict__ a_dst,
                              float* __restrict__ sc) {
    int n = blockIdx.x * (blockDim.x >> 5) + (threadIdx.x >> 5);
    int lane = threadIdx.x & 31;
    if (n >= NN) return;
    const float* row = hfeat + (size_t)n * (H * F);
#pragma unroll
    for (int h = 0; h < H; h++) {
        float ss = 0.f, sd = 0.f;
        for (int k = lane; k < F; k += 32) {
            float v = row[h * F + k];
            ss = fmaf(v, a_src[h * F + k], ss);
            sd = fmaf(v, a_dst[h * F + k], sd);
        }
#pragma unroll
        for (int o = 16; o; o >>= 1) {
            ss += __shfl_xor_sync(0xffffffffu, ss, o);
            sd += __shfl_xor_sync(0xffffffffu, sd, o);
        }
        if (lane == 0) {
            int idx = h * NN + n;
            sc[0 * HN + idx] = ss;
            sc[1 * HN + idx] = expf(ss);
            sc[2 * HN + idx] = expf(LRELU * ss);
            sc[3 * HN + idx] = sd;
            sc[4 * HN + idx] = expf(sd);
            sc[5 * HN + idx] = expf(LRELU * sd);
        }
    }
}

// ================ GAT aggregation via split-bf16 mma.sync ================
template <int F>
__device__ __forceinline__ void load_chunk(int t, int head, int i0, int c, int buf,
                                           char* BtB, unsigned* mk, float* edb,
                                           const __nv_bfloat16* hTh,
                                           const __nv_bfloat16* hTl,
                                           const float* sc) {
    constexpr int BT = F * 128;
    char* dsthi = BtB + buf * 2 * BT;
    char* dstlo = dsthi + BT;
    for (int idx = t; idx < F * 8; idx += 256) {
        int f = idx >> 3, q = idx & 7;
        uint32_t off = (uint32_t)(f * 128 + (((q ^ (f & 7)) << 4)));
        size_t src = (size_t)(head * F + f) * NN + c * 64 + q * 8;
        cp16(smem_u32(dsthi + off), hTh + src);
        cp16(smem_u32(dstlo + off), hTl + src);
    }
    if (t < 128) cp8(smem_u32(mk + buf * 256 + t * 2), &g_mask[(size_t)(i0 + t) * NW + c * 2]);
    if (t < 48) {
        int a = t >> 4, q = t & 15;
        cp16(smem_u32(edb + buf * 192 + a * 64 + q * 4),
             &sc[(size_t)(3 + a) * HN + head * NN + c * 64 + q * 4]);
    }
}

template <int F>
__global__ __launch_bounds__(256) void k_gat_hmma(const __nv_bfloat16* __restrict__ hTh,
                                                  const __nv_bfloat16* __restrict__ hTl,
                                                  const float* __restrict__ sc,
                                                  float* __restrict__ out) {
    constexpr int BT = F * 128;
    constexpr int MP = F / 32;
    extern __shared__ char smem[];
    char* BtB = smem;
    unsigned* mk = (unsigned*)(smem + 4 * BT);
    float* edb = (float*)(smem + 4 * BT + 2048);
    float* dsh = (float*)(smem + 4 * BT + 3584);
    float* dis = dsh + 128;

    int t = threadIdx.x, wid = t >> 5, lane = t & 31;
    int g = lane >> 2, tig = lane & 3;
    int rb = wid & 3, ch = wid >> 2;
    int head = blockIdx.y, i0 = blockIdx.x * 128;
    uint32_t sb = smem_u32(smem);

    int r00 = rb * 32 + g, r01 = r00 + 8, r10 = r00 + 16, r11 = r00 + 24;
    const float* scb = sc + head * NN + i0;
    float es00 = scb[r00], E00 = scb[HN + r00], e00 = scb[2 * HN + r00];
    float es01 = scb[r01], E01 = scb[HN + r01], e01 = scb[2 * HN + r01];
    float es10 = scb[r10], E10 = scb[HN + r10], e10 = scb[2 * HN + r10];
    float es11 = scb[r11], E11 = scb[HN + r11], e11 = scb[2 * HN + r11];

    int flr = ((lane >> 4) & 1) * 8 + (lane & 7);
    int qb = (lane >> 3) & 1;
    int sxw = flr & 7;
    uint32_t fcol = (uint32_t)((ch * (F / 2) + flr) * 128);

    float acc[2][2 * MP][4];
#pragma unroll
    for (int rt = 0; rt < 2; rt++)
#pragma unroll
        for (int nt = 0; nt < 2 * MP; nt++)
#pragma unroll
            for (int q = 0; q < 4; q++) acc[rt][nt][q] = 0.f;
    float d00 = 0.f, d01 = 0.f, d10 = 0.f, d11 = 0.f;

    load_chunk<F>(t, head, i0, 0, 0, BtB, mk, edb, hTh, hTl, sc);
    CP_COMMIT();

    for (int c = 0; c < 64; c++) {
        int b = c & 1;
        CP_WAIT0();
        __syncthreads();
        if (c < 63) {
            load_chunk<F>(t, head, i0, c + 1, b ^ 1, BtB, mk, edb, hTh, hTl, sc);
            CP_COMMIT();
        }
        unsigned* mkb = mk + b * 256;
        unsigned w00A = mkb[r00 * 2], w00B = mkb[r00 * 2 + 1];
        unsigned w01A = mkb[r01 * 2], w01B = mkb[r01 * 2 + 1];
        unsigned w10A = mkb[r10 * 2], w10B = mkb[r10 * 2 + 1];
        unsigned w11A = mkb[r11 * 2], w11B = mkb[r11 * 2 + 1];
        float* ed = edb + b * 192;
        uint32_t bufbase = sb + (uint32_t)(b * 2 * BT);
#pragma unroll
        for (int ks = 0; ks < 4; ks++) {
            int jb = ks * 16 + tig * 2;
            float2 erL = *(float2*)&ed[jb];
            float2 erH = *(float2*)&ed[jb + 8];
            float2 EvL = *(float2*)&ed[64 + jb];
            float2 EvH = *(float2*)&ed[64 + jb + 8];
            float2 e2L = *(float2*)&ed[128 + jb];
            float2 e2H = *(float2*)&ed[128 + jb + 8];
            int bit = (ks & 1) * 16 + tig * 2;
            unsigned w00 = (ks < 2) ? w00A : w00B;
            unsigned w01 = (ks < 2) ? w01A : w01B;
            unsigned w10 = (ks < 2) ? w10A : w10B;
            unsigned w11 = (ks < 2) ? w11A : w11B;

            uint32_t Ah[2][4], Al[2][4];
            {
                float a0 = wcalc(es00, E00, e00, erL.x, EvL.x, e2L.x, (w00 >> bit) & 1u);
                float a1 = wcalc(es00, E00, e00, erL.y, EvL.y, e2L.y, (w00 >> (bit + 1)) & 1u);
                float a2 = wcalc(es00, E00, e00, erH.x, EvH.x, e2H.x, (w00 >> (bit + 8)) & 1u);
                float a3 = wcalc(es00, E00, e00, erH.y, EvH.y, e2H.y, (w00 >> (bit + 9)) & 1u);
                float b0 = wcalc(es01, E01, e01, erL.x, EvL.x, e2L.x, (w01 >> bit) & 1u);
                float b1 = wcalc(es01, E01, e01, erL.y, EvL.y, e2L.y, (w01 >> (bit + 1)) & 1u);
                float b2 = wcalc(es01, E01, e01, erH.x, EvH.x, e2H.x, (w01 >> (bit + 8)) & 1u);
                float b3 = wcalc(es01, E01, e01, erH.y, EvH.y, e2H.y, (w01 >> (bit + 9)) & 1u);
                d00 += a0 + a1 + a2 + a3;
                d01 += b0 + b1 + b2 + b3;
                packhl(a0, a1, Ah[0][0], Al[0][0]);
                packhl(b0, b1, Ah[0][1], Al[0][1]);
                packhl(a2, a3, Ah[0][2], Al[0][2]);
                packhl(b2, b3, Ah[0][3], Al[0][3]);
            }
            {
                float a0 = wcalc(es10, E10, e10, erL.x, EvL.x, e2L.x, (w10 >> bit) & 1u);
                float a1 = wcalc(es10, E10, e10, erL.y, EvL.y, e2L.y, (w10 >> (bit + 1)) & 1u);
                float a2 = wcalc(es10, E10, e10, erH.x, EvH.x, e2H.x, (w10 >> (bit + 8)) & 1u);
                float a3 = wcalc(es10, E10, e10, erH.y, EvH.y, e2H.y, (w10 >> (bit + 9)) & 1u);
                float b0 = wcalc(es11, E11, e11, erL.x, EvL.x, e2L.x, (w11 >> bit) & 1u);
                float b1 = wcalc(es11, E11, e11, erL.y, EvL.y, e2L.y, (w11 >> (bit + 1)) & 1u);
                float b2 = wcalc(es11, E11, e11, erH.x, EvH.x, e2H.x, (w11 >> (bit + 8)) & 1u);
                float b3 = wcalc(es11, E11, e11, erH.y, EvH.y, e2H.y, (w11 >> (bit + 9)) & 1u);
                d10 += a0 + a1 + a2 + a3;
                d11 += b0 + b1 + b2 + b3;
                packhl(a0, a1, Ah[1][0], Al[1][0]);
                packhl(b0, b1, Ah[1][1], Al[1][1]);
                packhl(a2, a3, Ah[1][2], Al[1][2]);
                packhl(b2, b3, Ah[1][3], Al[1][3]);
            }
            uint32_t swz = (uint32_t)((((2 * ks + qb) ^ sxw) << 4));
#pragma unroll
            for (int mp = 0; mp < MP; mp++) {
                uint32_t ah = bufbase + fcol + (uint32_t)(mp * 2048) + swz;
                uint32_t al = ah + BT;
                uint32_t bh0, bh1, bh2, bh3, bl0, bl1, bl2, bl3;
                ldsm4(bh0, bh1, bh2, bh3, ah);
                ldsm4(bl0, bl1, bl2, bl3, al);
#pragma unroll
                for (int rt = 0; rt < 2; rt++) {
                    float* c0 = acc[rt][2 * mp];
                    float* c1 = acc[rt][2 * mp + 1];
                    mma16816(c0, Ah[rt][0], Ah[rt][1], Ah[rt][2], Ah[rt][3], bh0, bh1);
                    mma16816(c0, Ah[rt][0], Ah[rt][1], Ah[rt][2], Ah[rt][3], bl0, bl1);
                    mma16816(c0, Al[rt][0], Al[rt][1], Al[rt][2], Al[rt][3], bh0, bh1);
                    mma16816(c1, Ah[rt][0], Ah[rt][1], Ah[rt][2], Ah[rt][3], bh2, bh3);
                    mma16816(c1, Ah[rt][0], Ah[rt][1], Ah[rt][2], Ah[rt][3], bl2, bl3);
                    mma16816(c1, Al[rt][0], Al[rt][1], Al[rt][2], Al[rt][3], bh2, bh3);
                }
            }
        }
    }
    d00 += __shfl_xor_sync(0xffffffffu, d00, 1);
    d00 += __shfl_xor_sync(0xffffffffu, d00, 2);
    d01 += __shfl_xor_sync(0xffffffffu, d01, 1);
    d01 += __shfl_xor_sync(0xffffffffu, d01, 2);
    d10 += __shfl_xor_sync(0xffffffffu, d10, 1);
    d10 += __shfl_xor_sync(0xffffffffu, d10, 2);
    d11 += __shfl_xor_sync(0xffffffffu, d11, 1);
    d11 += __shfl_xor_sync(0xffffffffu, d11, 2);
    if (ch == 0 && tig == 0) {
        dsh[r00] = d00; dsh[r01] = d01; dsh[r10] = d10; dsh[r11] = d11;
    }
    __syncthreads();
    if (t < 128) dis[t] = 1.f / dsh[t];
    __syncthreads();
#pragma unroll
    for (int rt = 0; rt < 2; rt++) {
        int row = rb * 32 + rt * 16 + g;
        float iv0 = dis[row], iv1 = dis[row + 8];
#pragma unroll
        for (int nt = 0; nt < 2 * MP; nt++) {
            int col = head * F + ch * (F / 2) + nt * 8 + tig * 2;
            float2 v0 = make_float2(acc[rt][nt][0] * iv0, acc[rt][nt][1] * iv0);
            float2 v1 = make_float2(acc[rt][nt][2] * iv1, acc[rt][nt][3] * iv1);
            *(float2*)&out[(size_t)(i0 + row) * (H * F) + col] = v0;
            *(float2*)&out[(size_t)(i0 + row + 8) * (H * F) + col] = v1;
        }
    }
}

// ---------------- batchnorm: two-stage coalesced stats ----------------
template <int C>
__global__ void k_bn_part(const float* __restrict__ z, float* __restrict__ part) {
    constexpr int RL = 256 / C;
    int blk = blockIdx.x;
    int t = threadIdx.x;
    int col = t % C, rl = t / C;
    float s = 0.f, s2 = 0.f;
    for (int r = rl; r < 128; r += RL) {
        float v = z[(size_t)(blk * 128 + r) * C + col];
        s += v; s2 += v * v;
    }
    __shared__ float sh[256], sh2[256];
    sh[t] = s; sh2[t] = s2;
    __syncthreads();
    if (rl == 0) {
#pragma unroll
        for (int q = 1; q < RL; q++) { s += sh[q * C + col]; s2 += sh2[q * C + col]; }
        part[blk * 2 * C + col] = s;
        part[blk * 2 * C + C + col] = s2;
    }
}
template <int C>
__global__ void k_bn_fin(const float* __restrict__ part,
                         float* __restrict__ mean, float* __restrict__ rstd) {
    int c = threadIdx.x;
    if (c >= C) return;
    double s = 0.0, s2 = 0.0;
    for (int b = 0; b < 32; b++) { s += part[b * 2 * C + c]; s2 += part[b * 2 * C + C + c]; }
    double mu = s / NN;
    double var = s2 / NN - mu * mu;
    mean[c] = (float)mu;
    rstd[c] = rsqrtf((float)var + BN_EPS);
}

__global__ void k_bn_elu(const float* __restrict__ z, const float* __restrict__ mean,
                         const float* __restrict__ rstd, const float* __restrict__ gamma,
                         const float* __restrict__ beta, float* __restrict__ out, int C) {
    int idx = blockIdx.x * blockDim.x + threadIdx.x;
    int c = idx % C;
    float v = (z[idx] - mean[c]) * rstd[c] * gamma[c] + beta[c];
    out[idx] = v > 0.f ? v : (expf(v) - 1.f);
}

// ---------------- launch ----------------
extern "C" void kernel_launch(void* const* d_in, const int* in_sizes, int n_in,
                              void* d_out, int out_size) {
    const float* x   = (const float*)d_in[0];
    const int*   adj = (const int*)d_in[1];
    const float* W1  = (const float*)d_in[2];
    const float* a1s = (const float*)d_in[3];
    const float* a1d = (const float*)d_in[4];
    const float* lw1 = (const float*)d_in[5];
    const float* lb1 = (const float*)d_in[6];
    const float* g1  = (const float*)d_in[7];
    const float* be1 = (const float*)d_in[8];
    const float* W2  = (const float*)d_in[9];
    const float* a2s = (const float*)d_in[10];
    const float* a2d = (const float*)d_in[11];
    const float* lw2 = (const float*)d_in[12];
    const float* lb2 = (const float*)d_in[13];
    const float* g2  = (const float*)d_in[14];
    const float* be2 = (const float*)d_in[15];
    float* out = (float*)d_out;

    float *h1, *x1, *x2, *h2, *x3, *z4, *sc1, *sc2, *mean, *rstd, *bnp;
    __nv_bfloat16 *h1th, *h1tl, *h2th, *h2tl, *ah, *al, *wth, *wtl;
    cudaGetSymbolAddress((void**)&h1, g_h1);
    cudaGetSymbolAddress((void**)&x1, g_x1);
    cudaGetSymbolAddress((void**)&x2, g_x2);
    cudaGetSymbolAddress((void**)&h2, g_h2);
    cudaGetSymbolAddress((void**)&x3, g_x3);
    cudaGetSymbolAddress((void**)&z4, g_z4);
    cudaGetSymbolAddress((void**)&sc1, g_sc1);
    cudaGetSymbolAddress((void**)&sc2, g_sc2);
    cudaGetSymbolAddress((void**)&mean, g_mean);
    cudaGetSymbolAddress((void**)&rstd, g_rstd);
    cudaGetSymbolAddress((void**)&bnp, g_bnpart);
    cudaGetSymbolAddress((void**)&h1th, g_h1th);
    cudaGetSymbolAddress((void**)&h1tl, g_h1tl);
    cudaGetSymbolAddress((void**)&h2th, g_h2th);
    cudaGetSymbolAddress((void**)&h2tl, g_h2tl);
    cudaGetSymbolAddress((void**)&ah, g_ah);
    cudaGetSymbolAddress((void**)&al, g_al);
    cudaGetSymbolAddress((void**)&wth, g_wth);
    cudaGetSymbolAddress((void**)&wtl, g_wtl);

    const int SMEM1 = 4 * F1 * 128 + 3584 + 1024;
    const int SMEM2 = 4 * F2 * 128 + 3584 + 1024;
    const int SMEMG = 2 * GB_BUF;
    cudaFuncSetAttribute(k_gat_hmma<F1>, cudaFuncAttributeMaxDynamicSharedMemorySize, SMEM1);
    cudaFuncSetAttribute(k_gat_hmma<F2>, cudaFuncAttributeMaxDynamicSharedMemorySize, SMEM2);
    cudaFuncSetAttribute(k_gemm_hmma, cudaFuncAttributeMaxDynamicSharedMemorySize, SMEMG);

    k_pack_mask<<<(NN * NN) / 256, 256>>>(adj);

    // ---- h1 = x @ W1 (split-bf16 HMMA) ----
    k_split_bf16<<<(NN * IN_F / 4) / 256, 256>>>(x, ah, al);
    k_transpose_split<<<dim3(IN_F / 32, 512 / 32), dim3(32, 8)>>>(W1, wth, wtl, IN_F, 512);
    k_gemm_hmma<<<dim3(NN / 128, 512 / 64), 256, SMEMG>>>(ah, al, wth, wtl, nullptr, h1, IN_F, 512);

    k_attn_scores<F1><<<NN / 8, 256>>>(h1, a1s, a1d, sc1);
    k_transpose_split<<<dim3(NN / 32, 512 / 32), dim3(32, 8)>>>(h1, h1th, h1tl, NN, 512);

    k_gat_hmma<F1><<<dim3(NN / 128, H), 256, SMEM1>>>(h1th, h1tl, sc1, x1);

    // ---- z2 = x1 @ lw1 + lb1 (HMMA) ----
    k_split_bf16<<<(NN * 512 / 4) / 256, 256>>>(x1, ah, al);
    k_transpose_split<<<dim3(512 / 32, HID1 / 32), dim3(32, 8)>>>(lw1, wth, wtl, 512, HID1);
    k_gemm_hmma<<<dim3(NN / 128, HID1 / 64), 256, SMEMG>>>(ah, al, wth, wtl, lb1, x2, 512, HID1);

    k_bn_part<HID1><<<32, 256>>>(x2, bnp);
    k_bn_fin<HID1><<<1, 64>>>(bnp, mean, rstd);
    k_bn_elu<<<(NN * HID1) / 256, 256>>>(x2, mean, rstd, g1, be1, x2, HID1);

    // ---- h2 = x2 @ W2 (HMMA, K=64) ----
    k_split_bf16<<<(NN * HID1 / 4) / 256, 256>>>(x2, ah, al);
    k_transpose_split<<<dim3(HID1 / 32, 128 / 32), dim3(32, 8)>>>(W2, wth, wtl, HID1, 128);
    k_gemm_hmma<<<dim3(NN / 128, 128 / 64), 256, SMEMG>>>(ah, al, wth, wtl, nullptr, h2, HID1, 128);

    k_attn_scores<F2><<<NN / 8, 256>>>(h2, a2s, a2d, sc2);
    k_transpose_split<<<dim3(NN / 32, 128 / 32), dim3(32, 8)>>>(h2, h2th, h2tl, NN, 128);

    k_gat_hmma<F2><<<dim3(NN / 128, H), 256, SMEM2>>>(h2th, h2tl, sc2, x3);

    // ---- z4 = x3 @ lw2 + lb2 (fp32, larger blocks) ----
    k_gemm_bias<128, 16, 32, 4, 2><<<dim3(1, NN / 128), 256>>>(x3, lw2, lb2, z4, NN, OUT_F, 128);

    k_bn_part<OUT_F><<<32, 256>>>(z4, bnp);
    k_bn_fin<OUT_F><<<1, 64>>>(bnp, mean, rstd);
    k_bn_elu<<<(NN * OUT_F) / 256, 256>>>(z4, mean, rstd, g2, be2, out, OUT_F);
}

// round 7
// speedup vs baseline: 3.3745x; 1.0262x over previous
#include <cuda_runtime.h>
#include <cuda_bf16.h>
#include <math.h>
#include <stdint.h>

#define NN 4096
#define NW 128
#define H 4
#define F1 128
#define F2 32
#define HN (H * NN)
#define IN_F 512
#define HID1 64
#define OUT_F 16
#define LRELU 0.2f
#define BN_EPS 1e-5f

// ---------------- scratch ----------------
__device__ float         g_h1[NN * 512];
__device__ float         g_x1[NN * 512];
__device__ float         g_x2[NN * HID1];
__device__ float         g_h2[NN * 128];
__device__ float         g_x3[NN * 128];
__device__ float         g_z4[NN * OUT_F];
__device__ float         g_sc1[6 * HN];
__device__ float         g_sc2[6 * HN];
__device__ unsigned      g_mask[NN * NW];
__device__ float         g_mean[64], g_rstd[64];
__device__ float         g_bnpart[32 * 2 * 64];
__device__ __nv_bfloat16 g_h1th[512 * NN];
__device__ __nv_bfloat16 g_h1tl[512 * NN];
__device__ __nv_bfloat16 g_h2th[128 * NN];
__device__ __nv_bfloat16 g_h2tl[128 * NN];
__device__ __nv_bfloat16 g_ah[NN * 512];
__device__ __nv_bfloat16 g_al[NN * 512];
__device__ __nv_bfloat16 g_wth[512 * 512];
__device__ __nv_bfloat16 g_wtl[512 * 512];

// ================= helpers =================
__device__ __forceinline__ uint32_t smem_u32(const void* p) {
    uint32_t a;
    asm("{ .reg .u64 t; cvta.to.shared.u64 t, %1; cvt.u32.u64 %0, t; }" : "=r"(a) : "l"(p));
    return a;
}
__device__ __forceinline__ void cp16(uint32_t dst, const void* src) {
    asm volatile("cp.async.cg.shared.global [%0], [%1], 16;" :: "r"(dst), "l"(src));
}
__device__ __forceinline__ void cp8(uint32_t dst, const void* src) {
    asm volatile("cp.async.ca.shared.global [%0], [%1], 8;" :: "r"(dst), "l"(src));
}
#define CP_COMMIT() asm volatile("cp.async.commit_group;" ::: "memory")
#define CP_WAIT0()  asm volatile("cp.async.wait_group 0;" ::: "memory")

__device__ __forceinline__ void mma16816(float* c,
    uint32_t a0, uint32_t a1, uint32_t a2, uint32_t a3, uint32_t b0, uint32_t b1) {
    asm volatile(
        "mma.sync.aligned.m16n8k16.row.col.f32.bf16.bf16.f32 "
        "{%0,%1,%2,%3}, {%4,%5,%6,%7}, {%8,%9}, {%0,%1,%2,%3};"
        : "+f"(c[0]), "+f"(c[1]), "+f"(c[2]), "+f"(c[3])
        : "r"(a0), "r"(a1), "r"(a2), "r"(a3), "r"(b0), "r"(b1));
}
__device__ __forceinline__ void ldsm4(uint32_t& r0, uint32_t& r1, uint32_t& r2, uint32_t& r3,
                                      uint32_t addr) {
    asm volatile("ldmatrix.sync.aligned.m8n8.x4.shared.b16 {%0,%1,%2,%3}, [%4];"
                 : "=r"(r0), "=r"(r1), "=r"(r2), "=r"(r3) : "r"(addr));
}
// exp(lrelu(es+ed)) == max(exp(es)exp(ed), exp(.2es)exp(.2ed))  (exp monotone)
__device__ __forceinline__ float wmax(float E, float e, float Ev, float e2, unsigned bit) {
    float v = fmaxf(E * Ev, e * e2);
    return bit ? v : 0.f;
}
// truncation split: hi = bf16-truncate(a,b) packed via byte_perm; lo = rn(residual)
__device__ __forceinline__ void packtr(float a, float b, uint32_t& hi, uint32_t& lo) {
    uint32_t au = __float_as_uint(a), bu = __float_as_uint(b);
    hi = __byte_perm(au, bu, 0x7632);
    float la = a - __uint_as_float(au & 0xFFFF0000u);
    float lb = b - __uint_as_float(bu & 0xFFFF0000u);
    __nv_bfloat162 l2 = __floats2bfloat162_rn(la, lb);
    lo = *(uint32_t*)&l2;
}

// ---------------- adjacency -> bitmask ----------------
__global__ void k_pack_mask(const int* __restrict__ adj) {
    int gw   = (blockIdx.x * blockDim.x + threadIdx.x) >> 5;
    int lane = threadIdx.x & 31;
    int v = adj[(size_t)gw * 32 + lane];
    unsigned m = __ballot_sync(0xffffffffu, v > 0);
    if (lane == 0) g_mask[gw] = m;
}

// ---------------- elementwise fp32 -> bf16 hi/lo split ----------------
__global__ void k_split_bf16(const float* __restrict__ in,
                             __nv_bfloat16* __restrict__ oh,
                             __nv_bfloat16* __restrict__ ol) {
    int idx = blockIdx.x * blockDim.x + threadIdx.x;
    float4 v = ((const float4*)in)[idx];
    __nv_bfloat162 h0 = __floats2bfloat162_rn(v.x, v.y);
    __nv_bfloat162 h1 = __floats2bfloat162_rn(v.z, v.w);
    __nv_bfloat162 l0 = __floats2bfloat162_rn(v.x - __bfloat162float(h0.x),
                                              v.y - __bfloat162float(h0.y));
    __nv_bfloat162 l1 = __floats2bfloat162_rn(v.z - __bfloat162float(h1.x),
                                              v.w - __bfloat162float(h1.y));
    ((__nv_bfloat162*)oh)[idx * 2] = h0;
    ((__nv_bfloat162*)oh)[idx * 2 + 1] = h1;
    ((__nv_bfloat162*)ol)[idx * 2] = l0;
    ((__nv_bfloat162*)ol)[idx * 2 + 1] = l1;
}

// ---------------- transpose fp32 [R,C] -> bf16 hi/lo [C,R] ----------------
__global__ void k_transpose_split(const float* __restrict__ in,
                                  __nv_bfloat16* __restrict__ oh,
                                  __nv_bfloat16* __restrict__ ol, int R, int C) {
    __shared__ float tile[32][33];
    int r0 = blockIdx.x * 32, c0 = blockIdx.y * 32;
    int tx = threadIdx.x, ty = threadIdx.y;
#pragma unroll
    for (int q = 0; q < 4; q++)
        tile[ty * 4 + q][tx] = in[(size_t)(r0 + ty * 4 + q) * C + c0 + tx];
    __syncthreads();
#pragma unroll
    for (int q = 0; q < 4; q++) {
        float v = tile[tx][ty * 4 + q];
        __nv_bfloat16 hi = __float2bfloat16(v);
        float lo = v - __bfloat162float(hi);
        size_t o = (size_t)(c0 + ty * 4 + q) * R + r0 + tx;
        oh[o] = hi;
        ol[o] = __float2bfloat16(lo);
    }
}

// ================ split-bf16 HMMA GEMM (templated width) ================
// C[M,Ntot] = A[M,K] @ B^T + bias. BM=128, BK=64, BN templated (64 or 128).
// NWARP warps: 4 m-warps x (NWARP/4) n-warps, warp tile 32x32.
template <int BN, int NWARP>
__device__ __forceinline__ void gemm_load(int t, int m0, int n0, int c, int buf,
                                          uint32_t sb, int K,
                                          const __nv_bfloat16* Ah, const __nv_bfloat16* Al,
                                          const __nv_bfloat16* Bh, const __nv_bfloat16* Bl) {
    constexpr int AB = 16384;
    constexpr int BB = BN * 128;
    constexpr int BUF = 2 * AB + 2 * BB;
    uint32_t base = sb + buf * BUF;
#pragma unroll
    for (int idx = t; idx < 1024; idx += NWARP * 32) {
        int m = idx >> 3, q = idx & 7;
        uint32_t off = base + (uint32_t)(m * 128 + ((q ^ (m & 7)) << 4));
        size_t src = (size_t)(m0 + m) * K + c * 64 + q * 8;
        cp16(off, Ah + src);
        cp16(off + AB, Al + src);
    }
#pragma unroll
    for (int idx = t; idx < BN * 8; idx += NWARP * 32) {
        int n = idx >> 3, q = idx & 7;
        uint32_t off = base + 2 * AB + (uint32_t)(n * 128 + ((q ^ (n & 7)) << 4));
        size_t src = (size_t)(n0 + n) * K + c * 64 + q * 8;
        cp16(off, Bh + src);
        cp16(off + BB, Bl + src);
    }
}

template <int BN, int NWARP>
__global__ __launch_bounds__(NWARP * 32) void k_gemm_hmma(
    const __nv_bfloat16* __restrict__ Ah, const __nv_bfloat16* __restrict__ Al,
    const __nv_bfloat16* __restrict__ Bh, const __nv_bfloat16* __restrict__ Bl,
    const float* __restrict__ bias, float* __restrict__ C, int K, int Ntot) {
    constexpr int AB = 16384;
    constexpr int BB = BN * 128;
    constexpr int BUF = 2 * AB + 2 * BB;
    extern __shared__ char sm[];
    uint32_t sb = smem_u32(sm);
    int t = threadIdx.x, wid = t >> 5, lane = t & 31;
    int m0 = blockIdx.x * 128, n0 = blockIdx.y * BN;
    int wm = (wid & 3) * 32, wn = (wid >> 2) * 32;
    int g = lane >> 2, tig = lane & 3;
    int nc = K >> 6;

    int arow = (lane & 7) + ((lane >> 3) & 1) * 8;
    int ahalf = lane >> 4;
    int brow = ((lane >> 4) << 3) + (lane & 7);
    int bhalf = (lane >> 3) & 1;

    float acc[2][4][4];
#pragma unroll
    for (int mt = 0; mt < 2; mt++)
#pragma unroll
        for (int nt = 0; nt < 4; nt++)
#pragma unroll
            for (int q = 0; q < 4; q++) acc[mt][nt][q] = 0.f;

    gemm_load<BN, NWARP>(t, m0, n0, 0, 0, sb, K, Ah, Al, Bh, Bl);
    CP_COMMIT();

    for (int c = 0; c < nc; c++) {
        int buf = c & 1;
        CP_WAIT0();
        __syncthreads();
        if (c + 1 < nc) {
            gemm_load<BN, NWARP>(t, m0, n0, c + 1, buf ^ 1, sb, K, Ah, Al, Bh, Bl);
            CP_COMMIT();
        }
        uint32_t base = sb + buf * BUF;
#pragma unroll
        for (int ks = 0; ks < 4; ks++) {
            uint32_t ahf[2][4], alf[2][4], bhf[2][4], blf[2][4];
#pragma unroll
            for (int mt = 0; mt < 2; mt++) {
                int r = wm + mt * 16 + arow;
                int slot = 2 * ks + ahalf;
                uint32_t ad = base + (uint32_t)(r * 128 + ((slot ^ (r & 7)) << 4));
                ldsm4(ahf[mt][0], ahf[mt][1], ahf[mt][2], ahf[mt][3], ad);
                ldsm4(alf[mt][0], alf[mt][1], alf[mt][2], alf[mt][3], ad + AB);
            }
#pragma unroll
            for (int np = 0; np < 2; np++) {
                int r = wn + np * 16 + brow;
                int slot = 2 * ks + bhalf;
                uint32_t bd = base + 2 * AB + (uint32_t)(r * 128 + ((slot ^ (r & 7)) << 4));
                ldsm4(bhf[np][0], bhf[np][1], bhf[np][2], bhf[np][3], bd);
                ldsm4(blf[np][0], blf[np][1], blf[np][2], blf[np][3], bd + BB);
            }
#pragma unroll
            for (int mt = 0; mt < 2; mt++)
#pragma unroll
                for (int nt = 0; nt < 4; nt++) {
                    int np = nt >> 1, sel = (nt & 1) * 2;
                    uint32_t bh0 = bhf[np][sel], bh1 = bhf[np][sel + 1];
                    uint32_t bl0 = blf[np][sel], bl1 = blf[np][sel + 1];
                    float* cacc = acc[mt][nt];
                    mma16816(cacc, ahf[mt][0], ahf[mt][1], ahf[mt][2], ahf[mt][3], bh0, bh1);
                    mma16816(cacc, ahf[mt][0], ahf[mt][1], ahf[mt][2], ahf[mt][3], bl0, bl1);
                    mma16816(cacc, alf[mt][0], alf[mt][1], alf[mt][2], alf[mt][3], bh0, bh1);
                }
        }
    }
#pragma unroll
    for (int mt = 0; mt < 2; mt++)
#pragma unroll
        for (int nt = 0; nt < 4; nt++) {
            int row = m0 + wm + mt * 16 + g;
            int col = n0 + wn + nt * 8 + tig * 2;
            float bv0 = bias ? bias[col] : 0.f;
            float bv1 = bias ? bias[col + 1] : 0.f;
            float2 v0 = make_float2(acc[mt][nt][0] + bv0, acc[mt][nt][1] + bv1);
            float2 v1 = make_float2(acc[mt][nt][2] + bv0, acc[mt][nt][3] + bv1);
            *(float2*)&C[(size_t)row * Ntot + col] = v0;
            *(float2*)&C[(size_t)(row + 8) * Ntot + col] = v1;
        }
}

// ---------------- fp32 GEMM for lin2 ----------------
template <int BM, int BN, int BK, int TM, int TN>
__global__ void k_gemm_bias(const float* __restrict__ A, const float* __restrict__ B,
                            const float* __restrict__ bias, float* __restrict__ C,
                            int M, int Nn, int K) {
    constexpr int THREADS = (BM / TM) * (BN / TN);
    __shared__ float As[BM][BK + 1];
    __shared__ float Bs[BK][BN + 1];
    int tid = threadIdx.x;
    int rm = tid / (BN / TN);
    int rn = tid % (BN / TN);
    int m0 = blockIdx.y * BM, n0 = blockIdx.x * BN;
    float acc[TM][TN];
#pragma unroll
    for (int m = 0; m < TM; m++)
#pragma unroll
        for (int n = 0; n < TN; n++) acc[m][n] = 0.f;

    for (int k0 = 0; k0 < K; k0 += BK) {
        for (int idx = tid; idx < BM * BK; idx += THREADS) {
            int r = idx / BK, c = idx % BK;
            As[r][c] = A[(size_t)(m0 + r) * K + k0 + c];
        }
        for (int idx = tid; idx < BK * BN; idx += THREADS) {
            int r = idx / BN, c = idx % BN;
            Bs[r][c] = B[(size_t)(k0 + r) * Nn + n0 + c];
        }
        __syncthreads();
#pragma unroll
        for (int kk = 0; kk < BK; kk++) {
            float a[TM], b[TN];
#pragma unroll
            for (int m = 0; m < TM; m++) a[m] = As[rm * TM + m][kk];
#pragma unroll
            for (int n = 0; n < TN; n++) b[n] = Bs[kk][rn * TN + n];
#pragma unroll
            for (int m = 0; m < TM; m++)
#pragma unroll
                for (int n = 0; n < TN; n++) acc[m][n] = fmaf(a[m], b[n], acc[m][n]);
        }
        __syncthreads();
    }
#pragma unroll
    for (int m = 0; m < TM; m++) {
        int row = m0 + rm * TM + m;
#pragma unroll
        for (int n = 0; n < TN; n++) {
            int col = n0 + rn * TN + n;
            float v = acc[m][n];
            if (bias) v += bias[col];
            C[(size_t)row * Nn + col] = v;
        }
    }
}

// ---------------- per-node scores + precomputed exps ----------------
template <int F>
__global__ void k_attn_scores(const float* __restrict__ hfeat,
                              const float* __restrict__ a_src,
                              const float* __restrict__ a_dst,
                              float* __restrict__ sc) {
    int n = blockIdx.x * (blockDim.x >> 5) + (threadIdx.x >> 5);
    int lane = threadIdx.x & 31;
    if (n >= NN) return;
    const float* row = hfeat + (size_t)n * (H * F);
#pragma unroll
    for (int h = 0; h < H; h++) {
        float ss = 0.f, sd = 0.f;
        for (int k = lane; k < F; k += 32) {
            float v = row[h * F + k];
            ss = fmaf(v, a_src[h * F + k], ss);
            sd = fmaf(v, a_dst[h * F + k], sd);
        }
#pragma unroll
        for (int o = 16; o; o >>= 1) {
            ss += __shfl_xor_sync(0xffffffffu, ss, o);
            sd += __shfl_xor_sync(0xffffffffu, sd, o);
        }
        if (lane == 0) {
            int idx = h * NN + n;
            sc[0 * HN + idx] = ss;
            sc[1 * HN + idx] = expf(ss);
            sc[2 * HN + idx] = expf(LRELU * ss);
            sc[3 * HN + idx] = sd;
            sc[4 * HN + idx] = expf(sd);
            sc[5 * HN + idx] = expf(LRELU * sd);
        }
    }
}

// ================ GAT aggregation via split-bf16 mma.sync, 512 threads ================
// CTA: 128 rows x one head, 16 warps: 8 row-blocks (16 rows) x 2 col halves (F/2).
template <int F>
__device__ __forceinline__ void load_chunk(int t, int head, int i0, int c, int buf,
                                           char* BtB, unsigned* mk, float* edb,
                                           const __nv_bfloat16* hTh,
                                           const __nv_bfloat16* hTl,
                                           const float* sc) {
    constexpr int BT = F * 128;
    char* dsthi = BtB + buf * 2 * BT;
    char* dstlo = dsthi + BT;
    for (int idx = t; idx < F * 8; idx += 512) {
        int f = idx >> 3, q = idx & 7;
        uint32_t off = (uint32_t)(f * 128 + (((q ^ (f & 7)) << 4)));
        size_t src = (size_t)(head * F + f) * NN + c * 64 + q * 8;
        cp16(smem_u32(dsthi + off), hTh + src);
        cp16(smem_u32(dstlo + off), hTl + src);
    }
    if (t < 128) cp8(smem_u32(mk + buf * 256 + t * 2), &g_mask[(size_t)(i0 + t) * NW + c * 2]);
    if (t < 32) {
        int a = t >> 4, q = t & 15;  // a: 0=exp(ed), 1=exp(.2ed)
        cp16(smem_u32(edb + buf * 128 + a * 64 + q * 4),
             &sc[(size_t)(4 + a) * HN + head * NN + c * 64 + q * 4]);
    }
}

template <int F>
__global__ __launch_bounds__(512) void k_gat_hmma(const __nv_bfloat16* __restrict__ hTh,
                                                  const __nv_bfloat16* __restrict__ hTl,
                                                  const float* __restrict__ sc,
                                                  float* __restrict__ out) {
    constexpr int BT = F * 128;
    constexpr int MP = F / 32;
    extern __shared__ char smem[];
    char* BtB = smem;                               // [2][2][BT]
    unsigned* mk = (unsigned*)(smem + 4 * BT);      // [2][256]
    float* edb = (float*)(smem + 4 * BT + 2048);    // [2][128]
    float* dsh = (float*)(smem + 4 * BT + 3072);    // [128]
    float* dis = dsh + 128;

    int t = threadIdx.x, wid = t >> 5, lane = t & 31;
    int g = lane >> 2, tig = lane & 3;
    int rb = wid & 7, ch = wid >> 3;
    int head = blockIdx.y, i0 = blockIdx.x * 128;
    uint32_t sb = smem_u32(smem);

    int r0 = rb * 16 + g, r1 = r0 + 8;
    const float* scb = sc + head * NN + i0;
    float E0 = scb[HN + r0], e0 = scb[2 * HN + r0];
    float E1 = scb[HN + r1], e1 = scb[2 * HN + r1];

    int flr = ((lane >> 4) & 1) * 8 + (lane & 7);
    int qb = (lane >> 3) & 1;
    int sxw = flr & 7;
    uint32_t fcol = (uint32_t)((ch * (F / 2) + flr) * 128);

    float acc[2 * MP][4];
#pragma unroll
    for (int nt = 0; nt < 2 * MP; nt++)
#pragma unroll
        for (int q = 0; q < 4; q++) acc[nt][q] = 0.f;
    float d0 = 0.f, d1 = 0.f;

    load_chunk<F>(t, head, i0, 0, 0, BtB, mk, edb, hTh, hTl, sc);
    CP_COMMIT();

    for (int c = 0; c < 64; c++) {
        int b = c & 1;
        CP_WAIT0();
        __syncthreads();
        if (c < 63) {
            load_chunk<F>(t, head, i0, c + 1, b ^ 1, BtB, mk, edb, hTh, hTl, sc);
            CP_COMMIT();
        }
        unsigned* mkb = mk + b * 256;
        unsigned m0a = mkb[r0 * 2], m0b = mkb[r0 * 2 + 1];
        unsigned m1a = mkb[r1 * 2], m1b = mkb[r1 * 2 + 1];
        float* ed = edb + b * 128;
        uint32_t bufbase = sb + (uint32_t)(b * 2 * BT);
#pragma unroll
        for (int ks = 0; ks < 4; ks++) {
            int jb = ks * 16 + tig * 2;
            float2 EvL = *(float2*)&ed[jb];
            float2 EvH = *(float2*)&ed[jb + 8];
            float2 e2L = *(float2*)&ed[64 + jb];
            float2 e2H = *(float2*)&ed[64 + jb + 8];
            int bit = (ks & 1) * 16 + tig * 2;
            unsigned w0 = (ks < 2) ? m0a : m0b;
            unsigned w1 = (ks < 2) ? m1a : m1b;

            float a0 = wmax(E0, e0, EvL.x, e2L.x, (w0 >> bit) & 1u);
            float a1 = wmax(E0, e0, EvL.y, e2L.y, (w0 >> (bit + 1)) & 1u);
            float a2 = wmax(E0, e0, EvH.x, e2H.x, (w0 >> (bit + 8)) & 1u);
            float a3 = wmax(E0, e0, EvH.y, e2H.y, (w0 >> (bit + 9)) & 1u);
            float b0 = wmax(E1, e1, EvL.x, e2L.x, (w1 >> bit) & 1u);
            float b1 = wmax(E1, e1, EvL.y, e2L.y, (w1 >> (bit + 1)) & 1u);
            float b2 = wmax(E1, e1, EvH.x, e2H.x, (w1 >> (bit + 8)) & 1u);
            float b3 = wmax(E1, e1, EvH.y, e2H.y, (w1 >> (bit + 9)) & 1u);
            d0 += a0 + a1 + a2 + a3;
            d1 += b0 + b1 + b2 + b3;
            uint32_t Ah[4], Al[4];
            packtr(a0, a1, Ah[0], Al[0]);
            packtr(b0, b1, Ah[1], Al[1]);
            packtr(a2, a3, Ah[2], Al[2]);
            packtr(b2, b3, Ah[3], Al[3]);

            uint32_t swz = (uint32_t)((((2 * ks + qb) ^ sxw) << 4));
#pragma unroll
            for (int mp = 0; mp < MP; mp++) {
                uint32_t ah = bufbase + fcol + (uint32_t)(mp * 2048) + swz;
                uint32_t al = ah + BT;
                uint32_t bh0, bh1, bh2, bh3, bl0, bl1, bl2, bl3;
                ldsm4(bh0, bh1, bh2, bh3, ah);
                ldsm4(bl0, bl1, bl2, bl3, al);
                float* c0 = acc[2 * mp];
                float* c1 = acc[2 * mp + 1];
                mma16816(c0, Ah[0], Ah[1], Ah[2], Ah[3], bh0, bh1);
                mma16816(c0, Ah[0], Ah[1], Ah[2], Ah[3], bl0, bl1);
                mma16816(c0, Al[0], Al[1], Al[2], Al[3], bh0, bh1);
                mma16816(c1, Ah[0], Ah[1], Ah[2], Ah[3], bh2, bh3);
                mma16816(c1, Ah[0], Ah[1], Ah[2], Ah[3], bl2, bl3);
                mma16816(c1, Al[0], Al[1], Al[2], Al[3], bh2, bh3);
            }
        }
    }
    d0 += __shfl_xor_sync(0xffffffffu, d0, 1);
    d0 += __shfl_xor_sync(0xffffffffu, d0, 2);
    d1 += __shfl_xor_sync(0xffffffffu, d1, 1);
    d1 += __shfl_xor_sync(0xffffffffu, d1, 2);
    if (ch == 0 && tig == 0) { dsh[r0] = d0; dsh[r1] = d1; }
    __syncthreads();
    if (t < 128) dis[t] = 1.f / dsh[t];
    __syncthreads();
    float iv0 = dis[r0], iv1 = dis[r1];
#pragma unroll
    for (int nt = 0; nt < 2 * MP; nt++) {
        int col = head * F + ch * (F / 2) + nt * 8 + tig * 2;
        float2 v0 = make_float2(acc[nt][0] * iv0, acc[nt][1] * iv0);
        float2 v1 = make_float2(acc[nt][2] * iv1, acc[nt][3] * iv1);
        *(float2*)&out[(size_t)(i0 + r0) * (H * F) + col] = v0;
        *(float2*)&out[(size_t)(i0 + r1) * (H * F) + col] = v1;
    }
}

// ---------------- batchnorm: two-stage coalesced stats ----------------
template <int C>
__global__ void k_bn_part(const float* __restrict__ z, float* __restrict__ part) {
    constexpr int RL = 256 / C;
    int blk = blockIdx.x;
    int t = threadIdx.x;
    int col = t % C, rl = t / C;
    float s = 0.f, s2 = 0.f;
    for (int r = rl; r < 128; r += RL) {
        float v = z[(size_t)(blk * 128 + r) * C + col];
        s += v; s2 += v * v;
    }
    __shared__ float sh[256], sh2[256];
    sh[t] = s; sh2[t] = s2;
    __syncthreads();
    if (rl == 0) {
#pragma unroll
        for (int q = 1; q < RL; q++) { s += sh[q * C + col]; s2 += sh2[q * C + col]; }
        part[blk * 2 * C + col] = s;
        part[blk * 2 * C + C + col] = s2;
    }
}
template <int C>
__global__ void k_bn_fin(const float* __restrict__ part,
                         float* __restrict__ mean, float* __restrict__ rstd) {
    int c = threadIdx.x;
    if (c >= C) return;
    double s = 0.0, s2 = 0.0;
    for (int b = 0; b < 32; b++) { s += part[b * 2 * C + c]; s2 += part[b * 2 * C + C + c]; }
    double mu = s / NN;
    double var = s2 / NN - mu * mu;
    mean[c] = (float)mu;
    rstd[c] = rsqrtf((float)var + BN_EPS);
}

__global__ void k_bn_elu(const float* __restrict__ z, const float* __restrict__ mean,
                         const float* __restrict__ rstd, const float* __restrict__ gamma,
                         const float* __restrict__ beta, float* __restrict__ out, int C) {
    int idx = blockIdx.x * blockDim.x + threadIdx.x;
    int c = idx % C;
    float v = (z[idx] - mean[c]) * rstd[c] * gamma[c] + beta[c];
    out[idx] = v > 0.f ? v : (expf(v) - 1.f);
}

// ---------------- launch ----------------
extern "C" void kernel_launch(void* const* d_in, const int* in_sizes, int n_in,
                              void* d_out, int out_size) {
    const float* x   = (const float*)d_in[0];
    const int*   adj = (const int*)d_in[1];
    const float* W1  = (const float*)d_in[2];
    const float* a1s = (const float*)d_in[3];
    const float* a1d = (const float*)d_in[4];
    const float* lw1 = (const float*)d_in[5];
    const float* lb1 = (const float*)d_in[6];
    const float* g1  = (const float*)d_in[7];
    const float* be1 = (const float*)d_in[8];
    const float* W2  = (const float*)d_in[9];
    const float* a2s = (const float*)d_in[10];
    const float* a2d = (const float*)d_in[11];
    const float* lw2 = (const float*)d_in[12];
    const float* lb2 = (const float*)d_in[13];
    const float* g2  = (const float*)d_in[14];
    const float* be2 = (const float*)d_in[15];
    float* out = (float*)d_out;

    float *h1, *x1, *x2, *h2, *x3, *z4, *sc1, *sc2, *mean, *rstd, *bnp;
    __nv_bfloat16 *h1th, *h1tl, *h2th, *h2tl, *ah, *al, *wth, *wtl;
    cudaGetSymbolAddress((void**)&h1, g_h1);
    cudaGetSymbolAddress((void**)&x1, g_x1);
    cudaGetSymbolAddress((void**)&x2, g_x2);
    cudaGetSymbolAddress((void**)&h2, g_h2);
    cudaGetSymbolAddress((void**)&x3, g_x3);
    cudaGetSymbolAddress((void**)&z4, g_z4);
    cudaGetSymbolAddress((void**)&sc1, g_sc1);
    cudaGetSymbolAddress((void**)&sc2, g_sc2);
    cudaGetSymbolAddress((void**)&mean, g_mean);
    cudaGetSymbolAddress((void**)&rstd, g_rstd);
    cudaGetSymbolAddress((void**)&bnp, g_bnpart);
    cudaGetSymbolAddress((void**)&h1th, g_h1th);
    cudaGetSymbolAddress((void**)&h1tl, g_h1tl);
    cudaGetSymbolAddress((void**)&h2th, g_h2th);
    cudaGetSymbolAddress((void**)&h2tl, g_h2tl);
    cudaGetSymbolAddress((void**)&ah, g_ah);
    cudaGetSymbolAddress((void**)&al, g_al);
    cudaGetSymbolAddress((void**)&wth, g_wth);
    cudaGetSymbolAddress((void**)&wtl, g_wtl);

    const int SMEM1 = 4 * F1 * 128 + 4096;                 // 69632
    const int SMEM2 = 4 * F2 * 128 + 4096;                 // 20480
    const int SMEMG128 = 2 * (2 * 16384 + 2 * 128 * 128);  // 131072
    const int SMEMG64  = 2 * (2 * 16384 + 2 * 64 * 128);   // 98304
    cudaFuncSetAttribute(k_gat_hmma<F1>, cudaFuncAttributeMaxDynamicSharedMemorySize, SMEM1);
    cudaFuncSetAttribute(k_gat_hmma<F2>, cudaFuncAttributeMaxDynamicSharedMemorySize, SMEM2);
    cudaFuncSetAttribute((const void*)k_gemm_hmma<128, 16>,
                         cudaFuncAttributeMaxDynamicSharedMemorySize, SMEMG128);
    cudaFuncSetAttribute((const void*)k_gemm_hmma<64, 8>,
                         cudaFuncAttributeMaxDynamicSharedMemorySize, SMEMG64);

    k_pack_mask<<<(NN * NN) / 256, 256>>>(adj);

    // ---- h1 = x @ W1 ----
    k_split_bf16<<<(NN * IN_F / 4) / 256, 256>>>(x, ah, al);
    k_transpose_split<<<dim3(IN_F / 32, 512 / 32), dim3(32, 8)>>>(W1, wth, wtl, IN_F, 512);
    k_gemm_hmma<128, 16><<<dim3(NN / 128, 512 / 128), 512, SMEMG128>>>(
        ah, al, wth, wtl, nullptr, h1, IN_F, 512);

    k_attn_scores<F1><<<NN / 8, 256>>>(h1, a1s, a1d, sc1);
    k_transpose_split<<<dim3(NN / 32, 512 / 32), dim3(32, 8)>>>(h1, h1th, h1tl, NN, 512);

    k_gat_hmma<F1><<<dim3(NN / 128, H), 512, SMEM1>>>(h1th, h1tl, sc1, x1);

    // ---- z2 = x1 @ lw1 + lb1 ----
    k_split_bf16<<<(NN * 512 / 4) / 256, 256>>>(x1, ah, al);
    k_transpose_split<<<dim3(512 / 32, HID1 / 32), dim3(32, 8)>>>(lw1, wth, wtl, 512, HID1);
    k_gemm_hmma<64, 8><<<dim3(NN / 128, HID1 / 64), 256, SMEMG64>>>(
        ah, al, wth, wtl, lb1, x2, 512, HID1);

    k_bn_part<HID1><<<32, 256>>>(x2, bnp);
    k_bn_fin<HID1><<<1, 64>>>(bnp, mean, rstd);
    k_bn_elu<<<(NN * HID1) / 256, 256>>>(x2, mean, rstd, g1, be1, x2, HID1);

    // ---- h2 = x2 @ W2 ----
    k_split_bf16<<<(NN * HID1 / 4) / 256, 256>>>(x2, ah, al);
    k_transpose_split<<<dim3(HID1 / 32, 128 / 32), dim3(32, 8)>>>(W2, wth, wtl, HID1, 128);
    k_gemm_hmma<128, 16><<<dim3(NN / 128, 1), 512, SMEMG128>>>(
        ah, al, wth, wtl, nullptr, h2, HID1, 128);

    k_attn_scores<F2><<<NN / 8, 256>>>(h2, a2s, a2d, sc2);
    k_transpose_split<<<dim3(NN / 32, 128 / 32), dim3(32, 8)>>>(h2, h2th, h2tl, NN, 128);

    k_gat_hmma<F2><<<dim3(NN / 128, H), 512, SMEM2>>>(h2th, h2tl, sc2, x3);

    // ---- z4 = x3 @ lw2 + lb2 ----
    k_gemm_bias<128, 16, 32, 4, 2><<<dim3(1, NN / 128), 256>>>(x3, lw2, lb2, z4, NN, OUT_F, 128);

    k_bn_part<OUT_F><<<32, 256>>>(z4, bnp);
    k_bn_fin<OUT_F><<<1, 64>>>(bnp, mean, rstd);
    k_bn_elu<<<(NN * OUT_F) / 256, 256>>>(z4, mean, rstd, g2, be2, out, OUT_F);
}